// round 1
// baseline (speedup 1.0000x reference)
#include <cuda_runtime.h>
#include <cuda_bf16.h>
#include <math.h>

// Problem constants
#define SEQ    2048
#define DIM    4096
#define NH     32      // query heads
#define NKV    8       // kv heads
#define HD     128     // head dim
#define KVDIM  (NKV*HD)   // 1024

// ---------------------------------------------------------------------------
// Scratch (device globals; no allocation allowed)
// ---------------------------------------------------------------------------
static __device__ float g_q[SEQ * DIM];     // 32 MB
static __device__ float g_k[SEQ * KVDIM];   //  8 MB
static __device__ float g_v[SEQ * KVDIM];   //  8 MB
static __device__ float g_y[SEQ * DIM];     // 32 MB

// ---------------------------------------------------------------------------
// GEMM: C[M,N] = A[M,K] @ B[N,K]^T   (all row-major, fp32)
// Block tile 128x128, K-tile 16, 256 threads, 8x8 per thread.
// M,N multiples of 128; K multiple of 16 (true for all calls here).
// ---------------------------------------------------------------------------
__global__ void __launch_bounds__(256) gemm_nt_kernel(
    const float* __restrict__ A, const float* __restrict__ B,
    float* __restrict__ C, int M, int N, int K)
{
    __shared__ float As[16][132];   // +4 pad: conflict-free transposed stores
    __shared__ float Bs[16][132];

    const int tid = threadIdx.x;
    const int tx  = tid & 15;       // 0..15  (N direction)
    const int ty  = tid >> 4;       // 0..15  (M direction)
    const int row0 = blockIdx.y * 128;
    const int col0 = blockIdx.x * 128;

    const int lr  = tid >> 2;        // 0..63 : row within tile (two passes)
    const int lc4 = (tid & 3) * 4;   // 0,4,8,12 : k offset

    float acc[8][8];
#pragma unroll
    for (int i = 0; i < 8; i++)
#pragma unroll
        for (int j = 0; j < 8; j++) acc[i][j] = 0.f;

    for (int k0 = 0; k0 < K; k0 += 16) {
#pragma unroll
        for (int p = 0; p < 2; p++) {
            const int r = lr + p * 64;
            float4 va = *(const float4*)&A[(size_t)(row0 + r) * K + k0 + lc4];
            As[lc4 + 0][r] = va.x; As[lc4 + 1][r] = va.y;
            As[lc4 + 2][r] = va.z; As[lc4 + 3][r] = va.w;
            float4 vb = *(const float4*)&B[(size_t)(col0 + r) * K + k0 + lc4];
            Bs[lc4 + 0][r] = vb.x; Bs[lc4 + 1][r] = vb.y;
            Bs[lc4 + 2][r] = vb.z; Bs[lc4 + 3][r] = vb.w;
        }
        __syncthreads();

#pragma unroll
        for (int k = 0; k < 16; k++) {
            float a[8], b[8];
            *(float4*)&a[0] = *(const float4*)&As[k][ty * 8];
            *(float4*)&a[4] = *(const float4*)&As[k][ty * 8 + 4];
            *(float4*)&b[0] = *(const float4*)&Bs[k][tx * 8];
            *(float4*)&b[4] = *(const float4*)&Bs[k][tx * 8 + 4];
#pragma unroll
            for (int i = 0; i < 8; i++)
#pragma unroll
                for (int j = 0; j < 8; j++)
                    acc[i][j] = fmaf(a[i], b[j], acc[i][j]);
        }
        __syncthreads();
    }

#pragma unroll
    for (int i = 0; i < 8; i++) {
        const int r = row0 + ty * 8 + i;
        float4* cp = (float4*)&C[(size_t)r * N + col0 + tx * 8];
        cp[0] = make_float4(acc[i][0], acc[i][1], acc[i][2], acc[i][3]);
        cp[1] = make_float4(acc[i][4], acc[i][5], acc[i][6], acc[i][7]);
    }
}

// ---------------------------------------------------------------------------
// RoPE (in place): x is [SEQ, nheads, 128]; fc is [SEQ, 64, 2] (cos, sin)
// ---------------------------------------------------------------------------
__global__ void rope_kernel(float* __restrict__ x, const float* __restrict__ fc,
                            int nheads, int total)
{
    int idx = blockIdx.x * blockDim.x + threadIdx.x;
    if (idx >= total) return;
    const int i = idx & 63;
    const int h = (idx >> 6) % nheads;
    const int s = idx / (64 * nheads);
    const float c  = fc[(s * 64 + i) * 2 + 0];
    const float sn = fc[(s * 64 + i) * 2 + 1];
    float* p = x + ((size_t)s * nheads + h) * HD + 2 * i;
    const float x0 = p[0], x1 = p[1];
    p[0] = x0 * c - x1 * sn;
    p[1] = x1 * c + x0 * sn;
}

// ---------------------------------------------------------------------------
// Flash attention (fp32, causal, GQA rep=4). 64 q-rows x 64 k-rows tiles.
// Block: 256 threads as 16x16; each thread: 4 q-rows (score 4x4), O 4x8.
// Grid: (32 q-tiles, 32 heads).
// smem: Qs 64x128 | Ks 64x128 | Vs 64x128 | Ps 64x68  = 115712 B (dynamic)
// ---------------------------------------------------------------------------
#define ATTN_SMEM_BYTES ((3 * 64 * 128 + 64 * 68) * 4)

__global__ void __launch_bounds__(256) attn_kernel(
    const float* __restrict__ Q, const float* __restrict__ K,
    const float* __restrict__ V, float* __restrict__ Y)
{
    extern __shared__ float sm[];
    float* Qs = sm;                    // [64][128]
    float* Ks = Qs + 64 * 128;         // [64][128]
    float* Vs = Ks + 64 * 128;         // [64][128]
    float* Ps = Vs + 64 * 128;         // [64][68]

    const int qt  = blockIdx.x;        // q tile (0..31)
    const int h   = blockIdx.y;        // head (0..31)
    const int kvh = h >> 2;            // kv head
    const int tid = threadIdx.x;
    const int tx  = tid & 15;
    const int ty  = tid >> 4;

    // Load Q tile (64 rows x 128)
    for (int i = tid; i < 64 * 32; i += 256) {
        const int r = i >> 5, c4 = i & 31;
        ((float4*)(Qs + r * 128))[c4] =
            ((const float4*)(Q + (size_t)(qt * 64 + r) * DIM + h * HD))[c4];
    }

    float m[4], l[4], o[4][8];
#pragma unroll
    for (int i = 0; i < 4; i++) {
        m[i] = -1e30f; l[i] = 0.f;
#pragma unroll
        for (int c = 0; c < 8; c++) o[i][c] = 0.f;
    }

    const float scale = 0.08838834764831845f;  // 1/sqrt(128)

    for (int j = 0; j <= qt; j++) {
        __syncthreads();  // previous PV done (and Q load on first iter ordered below)
        for (int i = tid; i < 64 * 32; i += 256) {
            const int r = i >> 5, c4 = i & 31;
            ((float4*)(Ks + r * 128))[c4] =
                ((const float4*)(K + (size_t)(j * 64 + r) * KVDIM + kvh * HD))[c4];
            ((float4*)(Vs + r * 128))[c4] =
                ((const float4*)(V + (size_t)(j * 64 + r) * KVDIM + kvh * HD))[c4];
        }
        __syncthreads();

        // S = Q K^T  (4x4 per thread)
        float s[4][4];
#pragma unroll
        for (int i = 0; i < 4; i++)
#pragma unroll
            for (int jj = 0; jj < 4; jj++) s[i][jj] = 0.f;

        for (int k = 0; k < 128; k += 4) {
            float4 qa[4], kb[4];
#pragma unroll
            for (int i = 0; i < 4; i++)
                qa[i] = *(const float4*)(Qs + (ty * 4 + i) * 128 + k);
#pragma unroll
            for (int i = 0; i < 4; i++)
                kb[i] = *(const float4*)(Ks + (tx * 4 + i) * 128 + k);
#pragma unroll
            for (int i = 0; i < 4; i++)
#pragma unroll
                for (int jj = 0; jj < 4; jj++) {
                    s[i][jj] = fmaf(qa[i].x, kb[jj].x, s[i][jj]);
                    s[i][jj] = fmaf(qa[i].y, kb[jj].y, s[i][jj]);
                    s[i][jj] = fmaf(qa[i].z, kb[jj].z, s[i][jj]);
                    s[i][jj] = fmaf(qa[i].w, kb[jj].w, s[i][jj]);
                }
        }

        // scale + causal mask on the diagonal tile
#pragma unroll
        for (int i = 0; i < 4; i++)
#pragma unroll
            for (int jj = 0; jj < 4; jj++) s[i][jj] *= scale;
        if (j == qt) {
#pragma unroll
            for (int i = 0; i < 4; i++)
#pragma unroll
                for (int jj = 0; jj < 4; jj++)
                    if (tx * 4 + jj > ty * 4 + i) s[i][jj] = -1e30f;
        }

        // Online softmax update (row reductions across 16 lanes sharing ty)
#pragma unroll
        for (int i = 0; i < 4; i++) {
            float rm = fmaxf(fmaxf(s[i][0], s[i][1]), fmaxf(s[i][2], s[i][3]));
            rm = fmaxf(rm, __shfl_xor_sync(0xffffffffu, rm, 1));
            rm = fmaxf(rm, __shfl_xor_sync(0xffffffffu, rm, 2));
            rm = fmaxf(rm, __shfl_xor_sync(0xffffffffu, rm, 4));
            rm = fmaxf(rm, __shfl_xor_sync(0xffffffffu, rm, 8));
            const float mn = fmaxf(m[i], rm);
            const float alpha = __expf(m[i] - mn);
            float p0 = __expf(s[i][0] - mn);
            float p1 = __expf(s[i][1] - mn);
            float p2 = __expf(s[i][2] - mn);
            float p3 = __expf(s[i][3] - mn);
            float rs = p0 + p1 + p2 + p3;
            rs += __shfl_xor_sync(0xffffffffu, rs, 1);
            rs += __shfl_xor_sync(0xffffffffu, rs, 2);
            rs += __shfl_xor_sync(0xffffffffu, rs, 4);
            rs += __shfl_xor_sync(0xffffffffu, rs, 8);
            l[i] = l[i] * alpha + rs;
            m[i] = mn;
#pragma unroll
            for (int c = 0; c < 8; c++) o[i][c] *= alpha;
            float* pr = Ps + (ty * 4 + i) * 68 + tx * 4;
            pr[0] = p0; pr[1] = p1; pr[2] = p2; pr[3] = p3;
        }
        __syncthreads();

        // O += P @ V   (4 rows x 8 cols per thread)
        for (int kk = 0; kk < 64; kk++) {
            const float4 v0 = *(const float4*)(Vs + kk * 128 + tx * 8);
            const float4 v1 = *(const float4*)(Vs + kk * 128 + tx * 8 + 4);
#pragma unroll
            for (int i = 0; i < 4; i++) {
                const float p = Ps[(ty * 4 + i) * 68 + kk];
                o[i][0] = fmaf(p, v0.x, o[i][0]);
                o[i][1] = fmaf(p, v0.y, o[i][1]);
                o[i][2] = fmaf(p, v0.z, o[i][2]);
                o[i][3] = fmaf(p, v0.w, o[i][3]);
                o[i][4] = fmaf(p, v1.x, o[i][4]);
                o[i][5] = fmaf(p, v1.y, o[i][5]);
                o[i][6] = fmaf(p, v1.z, o[i][6]);
                o[i][7] = fmaf(p, v1.w, o[i][7]);
            }
        }
    }

    // Epilogue: normalize and store to Y[s, h*128 + d]
#pragma unroll
    for (int i = 0; i < 4; i++) {
        const float inv = 1.f / l[i];
        const int r = qt * 64 + ty * 4 + i;
        float* yp = Y + (size_t)r * DIM + h * HD + tx * 8;
        *(float4*)(yp)     = make_float4(o[i][0] * inv, o[i][1] * inv,
                                         o[i][2] * inv, o[i][3] * inv);
        *(float4*)(yp + 4) = make_float4(o[i][4] * inv, o[i][5] * inv,
                                         o[i][6] * inv, o[i][7] * inv);
    }
}

// ---------------------------------------------------------------------------
// Launch
// ---------------------------------------------------------------------------
extern "C" void kernel_launch(void* const* d_in, const int* in_sizes, int n_in,
                              void* d_out, int out_size)
{
    const float* x  = (const float*)d_in[0];
    const float* fc = (const float*)d_in[1];
    // d_in[2] is the dense mask; causal masking is applied analytically.
    const float* wq = (const float*)d_in[3];
    const float* wk = (const float*)d_in[4];
    const float* wv = (const float*)d_in[5];
    const float* wo = (const float*)d_in[6];
    float* out = (float*)d_out;

    float *Q, *Kp, *Vp, *Yp;
    cudaGetSymbolAddress((void**)&Q,  g_q);
    cudaGetSymbolAddress((void**)&Kp, g_k);
    cudaGetSymbolAddress((void**)&Vp, g_v);
    cudaGetSymbolAddress((void**)&Yp, g_y);

    const dim3 blk(256);

    // QKV projections
    gemm_nt_kernel<<<dim3(DIM / 128,  SEQ / 128), blk>>>(x, wq, Q,  SEQ, DIM,   DIM);
    gemm_nt_kernel<<<dim3(KVDIM / 128, SEQ / 128), blk>>>(x, wk, Kp, SEQ, KVDIM, DIM);
    gemm_nt_kernel<<<dim3(KVDIM / 128, SEQ / 128), blk>>>(x, wv, Vp, SEQ, KVDIM, DIM);

    // RoPE
    rope_kernel<<<(SEQ * NH  * 64 + 255) / 256, 256>>>(Q,  fc, NH,  SEQ * NH  * 64);
    rope_kernel<<<(SEQ * NKV * 64 + 255) / 256, 256>>>(Kp, fc, NKV, SEQ * NKV * 64);

    // Attention
    cudaFuncSetAttribute(attn_kernel, cudaFuncAttributeMaxDynamicSharedMemorySize,
                         ATTN_SMEM_BYTES);
    attn_kernel<<<dim3(SEQ / 64, NH), blk, ATTN_SMEM_BYTES>>>(Q, Kp, Vp, Yp);

    // Output projection
    gemm_nt_kernel<<<dim3(DIM / 128, SEQ / 128), blk>>>(Yp, wo, out, SEQ, DIM, DIM);
}

// round 3
// speedup vs baseline: 1.3640x; 1.3640x over previous
#include <cuda_runtime.h>
#include <cuda_bf16.h>
#include <math.h>
#include <stdint.h>

#define SEQ    2048
#define DIM    4096
#define NH     32
#define NKV    8
#define HD     128
#define KVDIM  (NKV*HD)

// ---------------------------------------------------------------------------
// Scratch (device globals; no allocation allowed)
// ---------------------------------------------------------------------------
static __device__ float g_q[SEQ * DIM];
static __device__ float g_k[SEQ * KVDIM];
static __device__ float g_v[SEQ * KVDIM];
static __device__ float g_y[SEQ * DIM];

static __device__ __nv_bfloat16 g_xh[SEQ * DIM],    g_xl[SEQ * DIM];
static __device__ __nv_bfloat16 g_wqh[DIM * DIM],   g_wql[DIM * DIM];
static __device__ __nv_bfloat16 g_wkh[KVDIM * DIM], g_wkl[KVDIM * DIM];
static __device__ __nv_bfloat16 g_wvh[KVDIM * DIM], g_wvl[KVDIM * DIM];
static __device__ __nv_bfloat16 g_woh[DIM * DIM],   g_wol[DIM * DIM];
static __device__ __nv_bfloat16 g_yh[SEQ * DIM],    g_yl[SEQ * DIM];

// ---------------------------------------------------------------------------
// Helpers
// ---------------------------------------------------------------------------
__device__ __forceinline__ uint32_t smem_u32(const void* p) {
    uint32_t a;
    asm("{ .reg .u64 t; cvta.to.shared.u64 t, %1; cvt.u32.u64 %0, t; }"
        : "=r"(a) : "l"(p));
    return a;
}

__device__ __forceinline__ void ldsm_x4(uint32_t* d, uint32_t addr) {
    asm volatile("ldmatrix.sync.aligned.m8n8.x4.shared.b16 {%0,%1,%2,%3}, [%4];"
                 : "=r"(d[0]), "=r"(d[1]), "=r"(d[2]), "=r"(d[3]) : "r"(addr));
}

__device__ __forceinline__ void mma16816(float* c, const uint32_t* a,
                                         uint32_t b0, uint32_t b1) {
    asm volatile(
        "mma.sync.aligned.m16n8k16.row.col.f32.bf16.bf16.f32 "
        "{%0,%1,%2,%3}, {%4,%5,%6,%7}, {%8,%9}, {%0,%1,%2,%3};"
        : "+f"(c[0]), "+f"(c[1]), "+f"(c[2]), "+f"(c[3])
        : "r"(a[0]), "r"(a[1]), "r"(a[2]), "r"(a[3]), "r"(b0), "r"(b1));
}

#define CP_ASYNC16(dst, src) \
    asm volatile("cp.async.cg.shared.global [%0], [%1], 16;" :: "r"(dst), "l"(src))
#define CP_COMMIT() asm volatile("cp.async.commit_group;" ::: "memory")
#define CP_WAIT0()  asm volatile("cp.async.wait_group 0;"  ::: "memory")

// ---------------------------------------------------------------------------
// Split fp32 -> (bf16 hi, bf16 lo)
// ---------------------------------------------------------------------------
__global__ void split_kernel(const float* __restrict__ in,
                             __nv_bfloat16* __restrict__ hi,
                             __nv_bfloat16* __restrict__ lo, int n4)
{
    int i = blockIdx.x * blockDim.x + threadIdx.x;
    if (i >= n4) return;
    float4 v = ((const float4*)in)[i];
    __nv_bfloat16 h0 = __float2bfloat16(v.x);
    __nv_bfloat16 h1 = __float2bfloat16(v.y);
    __nv_bfloat16 h2 = __float2bfloat16(v.z);
    __nv_bfloat16 h3 = __float2bfloat16(v.w);
    __nv_bfloat16 l0 = __float2bfloat16(v.x - __bfloat162float(h0));
    __nv_bfloat16 l1 = __float2bfloat16(v.y - __bfloat162float(h1));
    __nv_bfloat16 l2 = __float2bfloat16(v.z - __bfloat162float(h2));
    __nv_bfloat16 l3 = __float2bfloat16(v.w - __bfloat162float(h3));
    __nv_bfloat162* hp = (__nv_bfloat162*)hi;
    __nv_bfloat162* lp = (__nv_bfloat162*)lo;
    hp[2 * i]     = __nv_bfloat162(h0, h1);
    hp[2 * i + 1] = __nv_bfloat162(h2, h3);
    lp[2 * i]     = __nv_bfloat162(l0, l1);
    lp[2 * i + 1] = __nv_bfloat162(l2, l3);
}

// ---------------------------------------------------------------------------
// HMMA GEMM: C[M, Ntot] = (Ah+Al) @ (Bh+Bl)^T  via AhBh + AhBl + AlBh.
// A[M,4096] row-major (lds 4096), B[Ntot,4096] row-major (lds 4096).
// CTA tile 128x128, 8 warps (2x4), warp tile 64x32, K-chunk 32, 2-stage
// cp.async pipeline. smem row layout: 128B/row = [hi 32 bf16 | lo 32 bf16],
// SW128-swizzled (16B unit u at u ^ (row&7)).
// ---------------------------------------------------------------------------
#define GEMM_STAGE  32768                 // A 16KB + B 16KB
#define GEMM_SMEM   (2 * GEMM_STAGE + 1024)

__device__ __forceinline__ void stage_load(
    uint32_t s_stage,
    const __nv_bfloat16* __restrict__ Ah, const __nv_bfloat16* __restrict__ Al,
    const __nv_bfloat16* __restrict__ Bh, const __nv_bfloat16* __restrict__ Bl,
    int row0, int col0, int k0, int tid)
{
    const int r  = tid >> 1;        // 0..127
    const int h  = tid & 1;         // 0 = hi, 1 = lo
    const int sw = r & 7;
    const __nv_bfloat16* asrc = (h ? Al : Ah) + (size_t)(row0 + r) * DIM + k0;
    const __nv_bfloat16* bsrc = (h ? Bl : Bh) + (size_t)(col0 + r) * DIM + k0;
    const uint32_t arow = s_stage + r * 128;
    const uint32_t brow = s_stage + 16384 + r * 128;
#pragma unroll
    for (int u = 0; u < 4; u++) {
        const int phys = ((h * 4 + u) ^ sw) * 16;
        CP_ASYNC16(arow + phys, asrc + u * 8);
        CP_ASYNC16(brow + phys, bsrc + u * 8);
    }
}

__global__ void __launch_bounds__(256, 2)
gemm_hmma_kernel(const __nv_bfloat16* __restrict__ Ah,
                 const __nv_bfloat16* __restrict__ Al,
                 const __nv_bfloat16* __restrict__ Bh,
                 const __nv_bfloat16* __restrict__ Bl,
                 float* __restrict__ C, int Ntot)
{
    extern __shared__ char smraw[];
    const uint32_t sbase = (smem_u32(smraw) + 1023u) & ~1023u;

    const int tid = threadIdx.x;
    const int lid = tid & 31;
    const int wid = tid >> 5;
    const int wm  = wid & 1;         // 0..1  (M)
    const int wn  = wid >> 1;        // 0..3  (N)
    const int row0 = blockIdx.y * 128;
    const int col0 = blockIdx.x * 128;

    float acc[4][4][4];
#pragma unroll
    for (int i = 0; i < 4; i++)
#pragma unroll
        for (int j = 0; j < 4; j++)
#pragma unroll
            for (int q = 0; q < 4; q++) acc[i][j][q] = 0.f;

    const int NC = DIM / 32;   // 128 chunks

    stage_load(sbase, Ah, Al, Bh, Bl, row0, col0, 0, tid);
    CP_COMMIT();

    for (int c = 0; c < NC; c++) {
        CP_WAIT0();
        __syncthreads();
        if (c + 1 < NC) {
            stage_load(sbase + ((c + 1) & 1) * GEMM_STAGE,
                       Ah, Al, Bh, Bl, row0, col0, (c + 1) * 32, tid);
            CP_COMMIT();
        }
        const uint32_t aBase = sbase + (c & 1) * GEMM_STAGE;
        const uint32_t bBase = aBase + 16384;

#pragma unroll
        for (int ks = 0; ks < 2; ks++) {
            uint32_t ah[4][4], bh[2][4], bl[2][4];
            // A-hi frags (4 m16 tiles)
#pragma unroll
            for (int mt = 0; mt < 4; mt++) {
                const int r = wm * 64 + mt * 16 + (lid & 15);
                const int lu = ks * 2 + (lid >> 4);
                ldsm_x4(ah[mt], aBase + r * 128 + ((lu ^ (r & 7)) * 16));
            }
            // B-hi / B-lo frags (2 x4 each, covering 4 n8 tiles)
#pragma unroll
            for (int np = 0; np < 2; np++) {
                const int r  = wn * 32 + np * 16 + ((lid >> 4) & 1) * 8 + (lid & 7);
                const int lu = ks * 2 + ((lid >> 3) & 1);
                ldsm_x4(bh[np], bBase + r * 128 + ((lu ^ (r & 7)) * 16));
                ldsm_x4(bl[np], bBase + r * 128 + (((lu + 4) ^ (r & 7)) * 16));
            }
            // Ah*Bh and Ah*Bl
#pragma unroll
            for (int mt = 0; mt < 4; mt++)
#pragma unroll
                for (int nt = 0; nt < 4; nt++) {
                    mma16816(acc[mt][nt], ah[mt],
                             bh[nt >> 1][(nt & 1) * 2], bh[nt >> 1][(nt & 1) * 2 + 1]);
                    mma16816(acc[mt][nt], ah[mt],
                             bl[nt >> 1][(nt & 1) * 2], bl[nt >> 1][(nt & 1) * 2 + 1]);
                }
            // Al*Bh (reuse ah registers for Al)
#pragma unroll
            for (int mt = 0; mt < 4; mt++) {
                const int r = wm * 64 + mt * 16 + (lid & 15);
                const int lu = 4 + ks * 2 + (lid >> 4);
                ldsm_x4(ah[mt], aBase + r * 128 + ((lu ^ (r & 7)) * 16));
            }
#pragma unroll
            for (int mt = 0; mt < 4; mt++)
#pragma unroll
                for (int nt = 0; nt < 4; nt++)
                    mma16816(acc[mt][nt], ah[mt],
                             bh[nt >> 1][(nt & 1) * 2], bh[nt >> 1][(nt & 1) * 2 + 1]);
        }
        __syncthreads();
    }

    // Epilogue
#pragma unroll
    for (int mt = 0; mt < 4; mt++) {
        const int r = row0 + wm * 64 + mt * 16 + (lid >> 2);
#pragma unroll
        for (int nt = 0; nt < 4; nt++) {
            const int cc = col0 + wn * 32 + nt * 8 + (lid & 3) * 2;
            *(float2*)&C[(size_t)r * Ntot + cc] =
                make_float2(acc[mt][nt][0], acc[mt][nt][1]);
            *(float2*)&C[(size_t)(r + 8) * Ntot + cc] =
                make_float2(acc[mt][nt][2], acc[mt][nt][3]);
        }
    }
}

// ---------------------------------------------------------------------------
// RoPE (in place): x is [SEQ, nheads, 128]; fc is [SEQ, 64, 2] (cos, sin)
// ---------------------------------------------------------------------------
__global__ void rope_kernel(float* __restrict__ x, const float* __restrict__ fc,
                            int nheads, int total)
{
    int idx = blockIdx.x * blockDim.x + threadIdx.x;
    if (idx >= total) return;
    const int i = idx & 63;
    const int h = (idx >> 6) % nheads;
    const int s = idx / (64 * nheads);
    const float c  = fc[(s * 64 + i) * 2 + 0];
    const float sn = fc[(s * 64 + i) * 2 + 1];
    float* p = x + ((size_t)s * nheads + h) * HD + 2 * i;
    const float x0 = p[0], x1 = p[1];
    p[0] = x0 * c - x1 * sn;
    p[1] = x1 * c + x0 * sn;
}

// ---------------------------------------------------------------------------
// Flash attention (fp32, causal, GQA rep=4). 64x64 tiles, 256 threads.
// ---------------------------------------------------------------------------
#define ATTN_SMEM_BYTES ((3 * 64 * 128 + 64 * 68) * 4)

__global__ void __launch_bounds__(256) attn_kernel(
    const float* __restrict__ Q, const float* __restrict__ K,
    const float* __restrict__ V, float* __restrict__ Y)
{
    extern __shared__ float smf[];
    float* Qs = smf;
    float* Ks = Qs + 64 * 128;
    float* Vs = Ks + 64 * 128;
    float* Ps = Vs + 64 * 128;

    const int qt  = blockIdx.x;
    const int h   = blockIdx.y;
    const int kvh = h >> 2;
    const int tid = threadIdx.x;
    const int tx  = tid & 15;
    const int ty  = tid >> 4;

    for (int i = tid; i < 64 * 32; i += 256) {
        const int r = i >> 5, c4 = i & 31;
        ((float4*)(Qs + r * 128))[c4] =
            ((const float4*)(Q + (size_t)(qt * 64 + r) * DIM + h * HD))[c4];
    }

    float m[4], l[4], o[4][8];
#pragma unroll
    for (int i = 0; i < 4; i++) {
        m[i] = -1e30f; l[i] = 0.f;
#pragma unroll
        for (int c = 0; c < 8; c++) o[i][c] = 0.f;
    }

    const float scale = 0.08838834764831845f;

    for (int j = 0; j <= qt; j++) {
        __syncthreads();
        for (int i = tid; i < 64 * 32; i += 256) {
            const int r = i >> 5, c4 = i & 31;
            ((float4*)(Ks + r * 128))[c4] =
                ((const float4*)(K + (size_t)(j * 64 + r) * KVDIM + kvh * HD))[c4];
            ((float4*)(Vs + r * 128))[c4] =
                ((const float4*)(V + (size_t)(j * 64 + r) * KVDIM + kvh * HD))[c4];
        }
        __syncthreads();

        float s[4][4];
#pragma unroll
        for (int i = 0; i < 4; i++)
#pragma unroll
            for (int jj = 0; jj < 4; jj++) s[i][jj] = 0.f;

        for (int k = 0; k < 128; k += 4) {
            float4 qa[4], kb[4];
#pragma unroll
            for (int i = 0; i < 4; i++)
                qa[i] = *(const float4*)(Qs + (ty * 4 + i) * 128 + k);
#pragma unroll
            for (int i = 0; i < 4; i++)
                kb[i] = *(const float4*)(Ks + (tx * 4 + i) * 128 + k);
#pragma unroll
            for (int i = 0; i < 4; i++)
#pragma unroll
                for (int jj = 0; jj < 4; jj++) {
                    s[i][jj] = fmaf(qa[i].x, kb[jj].x, s[i][jj]);
                    s[i][jj] = fmaf(qa[i].y, kb[jj].y, s[i][jj]);
                    s[i][jj] = fmaf(qa[i].z, kb[jj].z, s[i][jj]);
                    s[i][jj] = fmaf(qa[i].w, kb[jj].w, s[i][jj]);
                }
        }

#pragma unroll
        for (int i = 0; i < 4; i++)
#pragma unroll
            for (int jj = 0; jj < 4; jj++) s[i][jj] *= scale;
        if (j == qt) {
#pragma unroll
            for (int i = 0; i < 4; i++)
#pragma unroll
                for (int jj = 0; jj < 4; jj++)
                    if (tx * 4 + jj > ty * 4 + i) s[i][jj] = -1e30f;
        }

#pragma unroll
        for (int i = 0; i < 4; i++) {
            float rm = fmaxf(fmaxf(s[i][0], s[i][1]), fmaxf(s[i][2], s[i][3]));
            rm = fmaxf(rm, __shfl_xor_sync(0xffffffffu, rm, 1));
            rm = fmaxf(rm, __shfl_xor_sync(0xffffffffu, rm, 2));
            rm = fmaxf(rm, __shfl_xor_sync(0xffffffffu, rm, 4));
            rm = fmaxf(rm, __shfl_xor_sync(0xffffffffu, rm, 8));
            const float mn = fmaxf(m[i], rm);
            const float alpha = __expf(m[i] - mn);
            float p0 = __expf(s[i][0] - mn);
            float p1 = __expf(s[i][1] - mn);
            float p2 = __expf(s[i][2] - mn);
            float p3 = __expf(s[i][3] - mn);
            float rs = p0 + p1 + p2 + p3;
            rs += __shfl_xor_sync(0xffffffffu, rs, 1);
            rs += __shfl_xor_sync(0xffffffffu, rs, 2);
            rs += __shfl_xor_sync(0xffffffffu, rs, 4);
            rs += __shfl_xor_sync(0xffffffffu, rs, 8);
            l[i] = l[i] * alpha + rs;
            m[i] = mn;
#pragma unroll
            for (int c = 0; c < 8; c++) o[i][c] *= alpha;
            float* pr = Ps + (ty * 4 + i) * 68 + tx * 4;
            pr[0] = p0; pr[1] = p1; pr[2] = p2; pr[3] = p3;
        }
        __syncthreads();

        for (int kk = 0; kk < 64; kk++) {
            const float4 v0 = *(const float4*)(Vs + kk * 128 + tx * 8);
            const float4 v1 = *(const float4*)(Vs + kk * 128 + tx * 8 + 4);
#pragma unroll
            for (int i = 0; i < 4; i++) {
                const float p = Ps[(ty * 4 + i) * 68 + kk];
                o[i][0] = fmaf(p, v0.x, o[i][0]);
                o[i][1] = fmaf(p, v0.y, o[i][1]);
                o[i][2] = fmaf(p, v0.z, o[i][2]);
                o[i][3] = fmaf(p, v0.w, o[i][3]);
                o[i][4] = fmaf(p, v1.x, o[i][4]);
                o[i][5] = fmaf(p, v1.y, o[i][5]);
                o[i][6] = fmaf(p, v1.z, o[i][6]);
                o[i][7] = fmaf(p, v1.w, o[i][7]);
            }
        }
    }

#pragma unroll
    for (int i = 0; i < 4; i++) {
        const float inv = 1.f / l[i];
        const int r = qt * 64 + ty * 4 + i;
        float* yp = Y + (size_t)r * DIM + h * HD + tx * 8;
        *(float4*)(yp)     = make_float4(o[i][0] * inv, o[i][1] * inv,
                                         o[i][2] * inv, o[i][3] * inv);
        *(float4*)(yp + 4) = make_float4(o[i][4] * inv, o[i][5] * inv,
                                         o[i][6] * inv, o[i][7] * inv);
    }
}

// ---------------------------------------------------------------------------
// Launch
// ---------------------------------------------------------------------------
extern "C" void kernel_launch(void* const* d_in, const int* in_sizes, int n_in,
                              void* d_out, int out_size)
{
    const float* x  = (const float*)d_in[0];
    const float* fc = (const float*)d_in[1];
    const float* wq = (const float*)d_in[3];
    const float* wk = (const float*)d_in[4];
    const float* wv = (const float*)d_in[5];
    const float* wo = (const float*)d_in[6];
    float* out = (float*)d_out;

    float *Q, *Kp, *Vp, *Yp;
    cudaGetSymbolAddress((void**)&Q,  g_q);
    cudaGetSymbolAddress((void**)&Kp, g_k);
    cudaGetSymbolAddress((void**)&Vp, g_v);
    cudaGetSymbolAddress((void**)&Yp, g_y);

    __nv_bfloat16 *xh, *xl, *wqh, *wql, *wkh, *wkl, *wvh, *wvl, *woh, *wol, *yh, *yl;
    cudaGetSymbolAddress((void**)&xh,  g_xh);  cudaGetSymbolAddress((void**)&xl,  g_xl);
    cudaGetSymbolAddress((void**)&wqh, g_wqh); cudaGetSymbolAddress((void**)&wql, g_wql);
    cudaGetSymbolAddress((void**)&wkh, g_wkh); cudaGetSymbolAddress((void**)&wkl, g_wkl);
    cudaGetSymbolAddress((void**)&wvh, g_wvh); cudaGetSymbolAddress((void**)&wvl, g_wvl);
    cudaGetSymbolAddress((void**)&woh, g_woh); cudaGetSymbolAddress((void**)&wol, g_wol);
    cudaGetSymbolAddress((void**)&yh,  g_yh);  cudaGetSymbolAddress((void**)&yl,  g_yl);

    cudaFuncSetAttribute(gemm_hmma_kernel,
                         cudaFuncAttributeMaxDynamicSharedMemorySize, GEMM_SMEM);
    cudaFuncSetAttribute(attn_kernel,
                         cudaFuncAttributeMaxDynamicSharedMemorySize, ATTN_SMEM_BYTES);

    const int T = 256;
    split_kernel<<<(SEQ * DIM / 4 + T - 1) / T, T>>>(x,  xh,  xl,  SEQ * DIM / 4);
    split_kernel<<<(DIM * DIM / 4 + T - 1) / T, T>>>(wq, wqh, wql, DIM * DIM / 4);
    split_kernel<<<(KVDIM * DIM / 4 + T - 1) / T, T>>>(wk, wkh, wkl, KVDIM * DIM / 4);
    split_kernel<<<(KVDIM * DIM / 4 + T - 1) / T, T>>>(wv, wvh, wvl, KVDIM * DIM / 4);
    split_kernel<<<(DIM * DIM / 4 + T - 1) / T, T>>>(wo, woh, wol, DIM * DIM / 4);

    // QKV projections (HMMA tensor cores)
    gemm_hmma_kernel<<<dim3(DIM / 128,   SEQ / 128), 256, GEMM_SMEM>>>(
        xh, xl, wqh, wql, Q,  DIM);
    gemm_hmma_kernel<<<dim3(KVDIM / 128, SEQ / 128), 256, GEMM_SMEM>>>(
        xh, xl, wkh, wkl, Kp, KVDIM);
    gemm_hmma_kernel<<<dim3(KVDIM / 128, SEQ / 128), 256, GEMM_SMEM>>>(
        xh, xl, wvh, wvl, Vp, KVDIM);

    // RoPE
    rope_kernel<<<(SEQ * NH  * 64 + 255) / 256, 256>>>(Q,  fc, NH,  SEQ * NH  * 64);
    rope_kernel<<<(SEQ * NKV * 64 + 255) / 256, 256>>>(Kp, fc, NKV, SEQ * NKV * 64);

    // Attention (fp32 flash)
    attn_kernel<<<dim3(SEQ / 64, NH), 256, ATTN_SMEM_BYTES>>>(Q, Kp, Vp, Yp);

    // Output projection
    split_kernel<<<(SEQ * DIM / 4 + T - 1) / T, T>>>(Yp, yh, yl, SEQ * DIM / 4);
    gemm_hmma_kernel<<<dim3(DIM / 128, SEQ / 128), 256, GEMM_SMEM>>>(
        yh, yl, woh, wol, out, DIM);
}

// round 4
// speedup vs baseline: 2.7919x; 2.0469x over previous
#include <cuda_runtime.h>
#include <cuda_bf16.h>
#include <math.h>
#include <stdint.h>

#define SEQ    2048
#define DIM    4096
#define NH     32
#define NKV    8
#define HD     128
#define KVDIM  (NKV*HD)

// ---------------------------------------------------------------------------
// Scratch (device globals; no allocation allowed)
// ---------------------------------------------------------------------------
static __device__ float g_q[SEQ * DIM];
static __device__ float g_k[SEQ * KVDIM];
static __device__ float g_v[SEQ * KVDIM];
static __device__ float g_y[SEQ * DIM];

static __device__ __nv_bfloat16 g_xh[SEQ * DIM],    g_xl[SEQ * DIM];
static __device__ __nv_bfloat16 g_wqh[DIM * DIM],   g_wql[DIM * DIM];
static __device__ __nv_bfloat16 g_wkh[KVDIM * DIM], g_wkl[KVDIM * DIM];
static __device__ __nv_bfloat16 g_wvh[KVDIM * DIM], g_wvl[KVDIM * DIM];
static __device__ __nv_bfloat16 g_woh[DIM * DIM],   g_wol[DIM * DIM];
static __device__ __nv_bfloat16 g_yh[SEQ * DIM],    g_yl[SEQ * DIM];

// Attention operands (bf16 splits)
static __device__ __nv_bfloat16 g_qh[SEQ * DIM],    g_ql[SEQ * DIM];
static __device__ __nv_bfloat16 g_kh[SEQ * KVDIM],  g_kl[SEQ * KVDIM];
static __device__ __nv_bfloat16 g_vth[KVDIM * SEQ], g_vtl[KVDIM * SEQ]; // [kvh*128+d][s]

// ---------------------------------------------------------------------------
// Helpers
// ---------------------------------------------------------------------------
__device__ __forceinline__ uint32_t smem_u32(const void* p) {
    uint32_t a;
    asm("{ .reg .u64 t; cvta.to.shared.u64 t, %1; cvt.u32.u64 %0, t; }"
        : "=r"(a) : "l"(p));
    return a;
}

__device__ __forceinline__ void ldsm_x4(uint32_t* d, uint32_t addr) {
    asm volatile("ldmatrix.sync.aligned.m8n8.x4.shared.b16 {%0,%1,%2,%3}, [%4];"
                 : "=r"(d[0]), "=r"(d[1]), "=r"(d[2]), "=r"(d[3]) : "r"(addr));
}

__device__ __forceinline__ void mma16816(float* c, const uint32_t* a,
                                         uint32_t b0, uint32_t b1) {
    asm volatile(
        "mma.sync.aligned.m16n8k16.row.col.f32.bf16.bf16.f32 "
        "{%0,%1,%2,%3}, {%4,%5,%6,%7}, {%8,%9}, {%0,%1,%2,%3};"
        : "+f"(c[0]), "+f"(c[1]), "+f"(c[2]), "+f"(c[3])
        : "r"(a[0]), "r"(a[1]), "r"(a[2]), "r"(a[3]), "r"(b0), "r"(b1));
}

#define CP_ASYNC16(dst, src) \
    asm volatile("cp.async.cg.shared.global [%0], [%1], 16;" :: "r"(dst), "l"(src))
#define CP_COMMIT() asm volatile("cp.async.commit_group;" ::: "memory")
#define CP_WAIT0()  asm volatile("cp.async.wait_group 0;"  ::: "memory")

__device__ __forceinline__ void split2(float a, __nv_bfloat16& h, __nv_bfloat16& l) {
    h = __float2bfloat16(a);
    l = __float2bfloat16(a - __bfloat162float(h));
}

// ---------------------------------------------------------------------------
// Split fp32 -> (bf16 hi, bf16 lo)
// ---------------------------------------------------------------------------
__global__ void split_kernel(const float* __restrict__ in,
                             __nv_bfloat16* __restrict__ hi,
                             __nv_bfloat16* __restrict__ lo, int n4)
{
    int i = blockIdx.x * blockDim.x + threadIdx.x;
    if (i >= n4) return;
    float4 v = ((const float4*)in)[i];
    __nv_bfloat16 h0, h1, h2, h3, l0, l1, l2, l3;
    split2(v.x, h0, l0); split2(v.y, h1, l1);
    split2(v.z, h2, l2); split2(v.w, h3, l3);
    __nv_bfloat162* hp = (__nv_bfloat162*)hi;
    __nv_bfloat162* lp = (__nv_bfloat162*)lo;
    hp[2 * i]     = __nv_bfloat162(h0, h1);
    hp[2 * i + 1] = __nv_bfloat162(h2, h3);
    lp[2 * i]     = __nv_bfloat162(l0, l1);
    lp[2 * i + 1] = __nv_bfloat162(l2, l3);
}

// ---------------------------------------------------------------------------
// RoPE + optional scale + split to bf16 hi/lo.  x: [SEQ, nheads, 128] fp32.
// ---------------------------------------------------------------------------
__global__ void rope_split_kernel(const float* __restrict__ x,
                                  const float* __restrict__ fc,
                                  __nv_bfloat16* __restrict__ oh,
                                  __nv_bfloat16* __restrict__ ol,
                                  int nheads, float scale, int total)
{
    int idx = blockIdx.x * blockDim.x + threadIdx.x;
    if (idx >= total) return;
    const int i = idx & 63;
    const int h = (idx >> 6) % nheads;
    const int s = idx / (64 * nheads);
    const float c  = fc[(s * 64 + i) * 2 + 0];
    const float sn = fc[(s * 64 + i) * 2 + 1];
    const size_t off = ((size_t)s * nheads + h) * HD + 2 * i;
    float2 v = *(const float2*)(x + off);
    float a = (v.x * c - v.y * sn) * scale;
    float b = (v.y * c + v.x * sn) * scale;
    __nv_bfloat16 ah, al, bh, bl;
    split2(a, ah, al); split2(b, bh, bl);
    *(__nv_bfloat162*)(oh + off) = __nv_bfloat162(ah, bh);
    *(__nv_bfloat162*)(ol + off) = __nv_bfloat162(al, bl);
}

// ---------------------------------------------------------------------------
// V transpose + split: in [s][kvh*128+d] fp32 -> out [kvh*128+d][s] bf16 hi/lo
// ---------------------------------------------------------------------------
__global__ void split_vt_kernel(const float* __restrict__ v,
                                __nv_bfloat16* __restrict__ vh,
                                __nv_bfloat16* __restrict__ vl)
{
    int idx = blockIdx.x * blockDim.x + threadIdx.x;  // d_lin*SEQ + s
    const int s = idx & (SEQ - 1);
    const int dl = idx >> 11;
    if (dl >= KVDIM) return;
    float val = v[(size_t)s * KVDIM + dl];
    __nv_bfloat16 h, l;
    split2(val, h, l);
    vh[idx] = h; vl[idx] = l;
}

// ---------------------------------------------------------------------------
// HMMA GEMM (unchanged from R3, validated)
// ---------------------------------------------------------------------------
#define GEMM_STAGE  32768
#define GEMM_SMEM   (2 * GEMM_STAGE + 1024)

__device__ __forceinline__ void stage_load(
    uint32_t s_stage,
    const __nv_bfloat16* __restrict__ Ah, const __nv_bfloat16* __restrict__ Al,
    const __nv_bfloat16* __restrict__ Bh, const __nv_bfloat16* __restrict__ Bl,
    int row0, int col0, int k0, int tid)
{
    const int r  = tid >> 1;
    const int h  = tid & 1;
    const int sw = r & 7;
    const __nv_bfloat16* asrc = (h ? Al : Ah) + (size_t)(row0 + r) * DIM + k0;
    const __nv_bfloat16* bsrc = (h ? Bl : Bh) + (size_t)(col0 + r) * DIM + k0;
    const uint32_t arow = s_stage + r * 128;
    const uint32_t brow = s_stage + 16384 + r * 128;
#pragma unroll
    for (int u = 0; u < 4; u++) {
        const int phys = ((h * 4 + u) ^ sw) * 16;
        CP_ASYNC16(arow + phys, asrc + u * 8);
        CP_ASYNC16(brow + phys, bsrc + u * 8);
    }
}

__global__ void __launch_bounds__(256, 2)
gemm_hmma_kernel(const __nv_bfloat16* __restrict__ Ah,
                 const __nv_bfloat16* __restrict__ Al,
                 const __nv_bfloat16* __restrict__ Bh,
                 const __nv_bfloat16* __restrict__ Bl,
                 float* __restrict__ C, int Ntot)
{
    extern __shared__ char smraw[];
    const uint32_t sbase = (smem_u32(smraw) + 1023u) & ~1023u;

    const int tid = threadIdx.x;
    const int lid = tid & 31;
    const int wid = tid >> 5;
    const int wm  = wid & 1;
    const int wn  = wid >> 1;
    const int row0 = blockIdx.y * 128;
    const int col0 = blockIdx.x * 128;

    float acc[4][4][4];
#pragma unroll
    for (int i = 0; i < 4; i++)
#pragma unroll
        for (int j = 0; j < 4; j++)
#pragma unroll
            for (int q = 0; q < 4; q++) acc[i][j][q] = 0.f;

    const int NC = DIM / 32;

    stage_load(sbase, Ah, Al, Bh, Bl, row0, col0, 0, tid);
    CP_COMMIT();

    for (int c = 0; c < NC; c++) {
        CP_WAIT0();
        __syncthreads();
        if (c + 1 < NC) {
            stage_load(sbase + ((c + 1) & 1) * GEMM_STAGE,
                       Ah, Al, Bh, Bl, row0, col0, (c + 1) * 32, tid);
            CP_COMMIT();
        }
        const uint32_t aBase = sbase + (c & 1) * GEMM_STAGE;
        const uint32_t bBase = aBase + 16384;

#pragma unroll
        for (int ks = 0; ks < 2; ks++) {
            uint32_t ah[4][4], bh[2][4], bl[2][4];
#pragma unroll
            for (int mt = 0; mt < 4; mt++) {
                const int r = wm * 64 + mt * 16 + (lid & 15);
                const int lu = ks * 2 + (lid >> 4);
                ldsm_x4(ah[mt], aBase + r * 128 + ((lu ^ (r & 7)) * 16));
            }
#pragma unroll
            for (int np = 0; np < 2; np++) {
                const int r  = wn * 32 + np * 16 + ((lid >> 4) & 1) * 8 + (lid & 7);
                const int lu = ks * 2 + ((lid >> 3) & 1);
                ldsm_x4(bh[np], bBase + r * 128 + ((lu ^ (r & 7)) * 16));
                ldsm_x4(bl[np], bBase + r * 128 + (((lu + 4) ^ (r & 7)) * 16));
            }
#pragma unroll
            for (int mt = 0; mt < 4; mt++)
#pragma unroll
                for (int nt = 0; nt < 4; nt++) {
                    mma16816(acc[mt][nt], ah[mt],
                             bh[nt >> 1][(nt & 1) * 2], bh[nt >> 1][(nt & 1) * 2 + 1]);
                    mma16816(acc[mt][nt], ah[mt],
                             bl[nt >> 1][(nt & 1) * 2], bl[nt >> 1][(nt & 1) * 2 + 1]);
                }
#pragma unroll
            for (int mt = 0; mt < 4; mt++) {
                const int r = wm * 64 + mt * 16 + (lid & 15);
                const int lu = 4 + ks * 2 + (lid >> 4);
                ldsm_x4(ah[mt], aBase + r * 128 + ((lu ^ (r & 7)) * 16));
            }
#pragma unroll
            for (int mt = 0; mt < 4; mt++)
#pragma unroll
                for (int nt = 0; nt < 4; nt++)
                    mma16816(acc[mt][nt], ah[mt],
                             bh[nt >> 1][(nt & 1) * 2], bh[nt >> 1][(nt & 1) * 2 + 1]);
        }
        __syncthreads();
    }

#pragma unroll
    for (int mt = 0; mt < 4; mt++) {
        const int r = row0 + wm * 64 + mt * 16 + (lid >> 2);
#pragma unroll
        for (int nt = 0; nt < 4; nt++) {
            const int cc = col0 + wn * 32 + nt * 8 + (lid & 3) * 2;
            *(float2*)&C[(size_t)r * Ntot + cc] =
                make_float2(acc[mt][nt][0], acc[mt][nt][1]);
            *(float2*)&C[(size_t)(r + 8) * Ntot + cc] =
                make_float2(acc[mt][nt][2], acc[mt][nt][3]);
        }
    }
}

// ---------------------------------------------------------------------------
// HMMA flash attention. Br=64 (4 warps x m16), Bc=64, causal, GQA rep 4.
// S = Qh.Kh + Qh.Kl + Ql.Kh  (scale folded into Q);  O = P.Vh + P.Vl.
// smem: Qh,Ql,Kh,Kl: [64 rows][256B] swizzled; Vth,Vtl: [128 rows][128B].
// ---------------------------------------------------------------------------
#define AT_QH 0
#define AT_QL 16384
#define AT_KH 32768
#define AT_KL 49152
#define AT_VH 65536
#define AT_VL 81920
#define AT_SMEM 98304

__global__ void __launch_bounds__(128)
attn_hmma_kernel(const __nv_bfloat16* __restrict__ Qh,
                 const __nv_bfloat16* __restrict__ Ql,
                 const __nv_bfloat16* __restrict__ Kh,
                 const __nv_bfloat16* __restrict__ Kl,
                 const __nv_bfloat16* __restrict__ Vth,
                 const __nv_bfloat16* __restrict__ Vtl,
                 float* __restrict__ Y)
{
    extern __shared__ char smraw[];
    char* sm = smraw;
    const uint32_t sb = smem_u32(smraw);

    const int qt  = blockIdx.x;
    const int h   = blockIdx.y;
    const int kvh = h >> 2;
    const int tid = threadIdx.x;
    const int lid = tid & 31;
    const int wid = tid >> 5;
    const int qrow0 = qt * 64;

    // Load Q tile (64 x 128 bf16, hi+lo), swizzled rows of 16 x 16B units
    for (int idx = tid; idx < 1024; idx += 128) {
        const int r = idx >> 4, u = idx & 15;
        const int phys = ((u ^ (r & 7)) * 16);
        const size_t g = ((size_t)(qrow0 + r) * NH + h) * HD + u * 8;
        *(float4*)(sm + AT_QH + r * 256 + phys) = *(const float4*)(Qh + g);
        *(float4*)(sm + AT_QL + r * 256 + phys) = *(const float4*)(Ql + g);
    }

    float o[16][4];
#pragma unroll
    for (int dt = 0; dt < 16; dt++)
#pragma unroll
        for (int q = 0; q < 4; q++) o[dt][q] = 0.f;
    float mA = -1e30f, mB = -1e30f, lA = 0.f, lB = 0.f;

    const int g = lid >> 2;               // row-in-8 group
    const int cA = (lid & 3) * 2;         // col pair base

    for (int j = 0; j <= qt; j++) {
        __syncthreads();
        // Load K (64x128 hi/lo) and Vt (128x64 hi/lo)
        for (int idx = tid; idx < 1024; idx += 128) {
            const int r = idx >> 4, u = idx & 15;
            const int phys = ((u ^ (r & 7)) * 16);
            const size_t gk = ((size_t)(j * 64 + r) * NKV + kvh) * HD + u * 8;
            *(float4*)(sm + AT_KH + r * 256 + phys) = *(const float4*)(Kh + gk);
            *(float4*)(sm + AT_KL + r * 256 + phys) = *(const float4*)(Kl + gk);
        }
        for (int idx = tid; idx < 1024; idx += 128) {
            const int r = idx >> 3, u = idx & 7;
            const int phys = ((u ^ (r & 7)) * 16);
            const size_t gv = ((size_t)(kvh * 128 + r)) * SEQ + j * 64 + u * 8;
            *(float4*)(sm + AT_VH + r * 128 + phys) = *(const float4*)(Vth + gv);
            *(float4*)(sm + AT_VL + r * 128 + phys) = *(const float4*)(Vtl + gv);
        }
        __syncthreads();

        // ---- S = Q K^T (split) ----
        float s[8][4];
#pragma unroll
        for (int nt = 0; nt < 8; nt++)
#pragma unroll
            for (int q = 0; q < 4; q++) s[nt][q] = 0.f;

#pragma unroll
        for (int kc = 0; kc < 8; kc++) {
            uint32_t qhf[4], qlf[4];
            const int rA = wid * 16 + (lid & 15);
            const int uA = kc * 2 + (lid >> 4);
            ldsm_x4(qhf, sb + AT_QH + rA * 256 + ((uA ^ (rA & 7)) * 16));
            ldsm_x4(qlf, sb + AT_QL + rA * 256 + ((uA ^ (rA & 7)) * 16));
#pragma unroll
            for (int np = 0; np < 4; np++) {
                uint32_t khf[4], klf[4];
                const int rB = np * 16 + ((lid >> 4) & 1) * 8 + (lid & 7);
                const int uB = kc * 2 + ((lid >> 3) & 1);
                ldsm_x4(khf, sb + AT_KH + rB * 256 + ((uB ^ (rB & 7)) * 16));
                ldsm_x4(klf, sb + AT_KL + rB * 256 + ((uB ^ (rB & 7)) * 16));
#pragma unroll
                for (int hf = 0; hf < 2; hf++) {
                    const int nt = np * 2 + hf;
                    mma16816(s[nt], qhf, khf[hf * 2], khf[hf * 2 + 1]);
                    mma16816(s[nt], qhf, klf[hf * 2], klf[hf * 2 + 1]);
                    mma16816(s[nt], qlf, khf[hf * 2], khf[hf * 2 + 1]);
                }
            }
        }

        // ---- causal mask on diagonal tile ----
        if (j == qt) {
            const int rowA = wid * 16 + g;       // local row (tile base equal)
#pragma unroll
            for (int nt = 0; nt < 8; nt++) {
                const int col = nt * 8 + cA;
                if (col     > rowA)     s[nt][0] = -1e30f;
                if (col + 1 > rowA)     s[nt][1] = -1e30f;
                if (col     > rowA + 8) s[nt][2] = -1e30f;
                if (col + 1 > rowA + 8) s[nt][3] = -1e30f;
            }
        }

        // ---- online softmax ----
        float mxA = -1e30f, mxB = -1e30f;
#pragma unroll
        for (int nt = 0; nt < 8; nt++) {
            mxA = fmaxf(mxA, fmaxf(s[nt][0], s[nt][1]));
            mxB = fmaxf(mxB, fmaxf(s[nt][2], s[nt][3]));
        }
        mxA = fmaxf(mxA, __shfl_xor_sync(0xffffffffu, mxA, 1));
        mxA = fmaxf(mxA, __shfl_xor_sync(0xffffffffu, mxA, 2));
        mxB = fmaxf(mxB, __shfl_xor_sync(0xffffffffu, mxB, 1));
        mxB = fmaxf(mxB, __shfl_xor_sync(0xffffffffu, mxB, 2));
        const float mnA = fmaxf(mA, mxA), mnB = fmaxf(mB, mxB);
        const float alA = __expf(mA - mnA), alB = __expf(mB - mnB);

        uint32_t p[8][2];
        float rsA = 0.f, rsB = 0.f;
#pragma unroll
        for (int nt = 0; nt < 8; nt++) {
            float p0 = __expf(s[nt][0] - mnA);
            float p1 = __expf(s[nt][1] - mnA);
            float p2 = __expf(s[nt][2] - mnB);
            float p3 = __expf(s[nt][3] - mnB);
            uint32_t pa, pb;
            asm("cvt.rn.bf16x2.f32 %0, %1, %2;" : "=r"(pa) : "f"(p1), "f"(p0));
            asm("cvt.rn.bf16x2.f32 %0, %1, %2;" : "=r"(pb) : "f"(p3), "f"(p2));
            p[nt][0] = pa; p[nt][1] = pb;
            __nv_bfloat162 ta = *reinterpret_cast<__nv_bfloat162*>(&pa);
            __nv_bfloat162 tb = *reinterpret_cast<__nv_bfloat162*>(&pb);
            rsA += __bfloat162float(ta.x) + __bfloat162float(ta.y);
            rsB += __bfloat162float(tb.x) + __bfloat162float(tb.y);
        }
        rsA += __shfl_xor_sync(0xffffffffu, rsA, 1);
        rsA += __shfl_xor_sync(0xffffffffu, rsA, 2);
        rsB += __shfl_xor_sync(0xffffffffu, rsB, 1);
        rsB += __shfl_xor_sync(0xffffffffu, rsB, 2);
        lA = lA * alA + rsA;  mA = mnA;
        lB = lB * alB + rsB;  mB = mnB;

#pragma unroll
        for (int dt = 0; dt < 16; dt++) {
            o[dt][0] *= alA; o[dt][1] *= alA;
            o[dt][2] *= alB; o[dt][3] *= alB;
        }

        // ---- O += P @ V (split V) ----
#pragma unroll
        for (int kc = 0; kc < 4; kc++) {
            uint32_t a[4] = { p[2 * kc][0], p[2 * kc][1],
                              p[2 * kc + 1][0], p[2 * kc + 1][1] };
#pragma unroll
            for (int dp = 0; dp < 8; dp++) {
                uint32_t vhf[4], vlf[4];
                const int rB = dp * 16 + ((lid >> 4) & 1) * 8 + (lid & 7);
                const int uB = kc * 2 + ((lid >> 3) & 1);
                ldsm_x4(vhf, sb + AT_VH + rB * 128 + ((uB ^ (rB & 7)) * 16));
                ldsm_x4(vlf, sb + AT_VL + rB * 128 + ((uB ^ (rB & 7)) * 16));
#pragma unroll
                for (int hf = 0; hf < 2; hf++) {
                    const int dt = dp * 2 + hf;
                    mma16816(o[dt], a, vhf[hf * 2], vhf[hf * 2 + 1]);
                    mma16816(o[dt], a, vlf[hf * 2], vlf[hf * 2 + 1]);
                }
            }
        }
    }

    // Epilogue
    const float invA = 1.f / lA, invB = 1.f / lB;
    const int rowA = qrow0 + wid * 16 + g;
#pragma unroll
    for (int dt = 0; dt < 16; dt++) {
        const int d = h * HD + dt * 8 + cA;
        *(float2*)&Y[(size_t)rowA * DIM + d] =
            make_float2(o[dt][0] * invA, o[dt][1] * invA);
        *(float2*)&Y[(size_t)(rowA + 8) * DIM + d] =
            make_float2(o[dt][2] * invB, o[dt][3] * invB);
    }
}

// ---------------------------------------------------------------------------
// Launch
// ---------------------------------------------------------------------------
extern "C" void kernel_launch(void* const* d_in, const int* in_sizes, int n_in,
                              void* d_out, int out_size)
{
    const float* x  = (const float*)d_in[0];
    const float* fc = (const float*)d_in[1];
    const float* wq = (const float*)d_in[3];
    const float* wk = (const float*)d_in[4];
    const float* wv = (const float*)d_in[5];
    const float* wo = (const float*)d_in[6];
    float* out = (float*)d_out;

    float *Q, *Kp, *Vp, *Yp;
    cudaGetSymbolAddress((void**)&Q,  g_q);
    cudaGetSymbolAddress((void**)&Kp, g_k);
    cudaGetSymbolAddress((void**)&Vp, g_v);
    cudaGetSymbolAddress((void**)&Yp, g_y);

    __nv_bfloat16 *xh, *xl, *wqh, *wql, *wkh, *wkl, *wvh, *wvl, *woh, *wol, *yh, *yl;
    __nv_bfloat16 *qh, *ql, *kh, *kl, *vth, *vtl;
    cudaGetSymbolAddress((void**)&xh,  g_xh);  cudaGetSymbolAddress((void**)&xl,  g_xl);
    cudaGetSymbolAddress((void**)&wqh, g_wqh); cudaGetSymbolAddress((void**)&wql, g_wql);
    cudaGetSymbolAddress((void**)&wkh, g_wkh); cudaGetSymbolAddress((void**)&wkl, g_wkl);
    cudaGetSymbolAddress((void**)&wvh, g_wvh); cudaGetSymbolAddress((void**)&wvl, g_wvl);
    cudaGetSymbolAddress((void**)&woh, g_woh); cudaGetSymbolAddress((void**)&wol, g_wol);
    cudaGetSymbolAddress((void**)&yh,  g_yh);  cudaGetSymbolAddress((void**)&yl,  g_yl);
    cudaGetSymbolAddress((void**)&qh,  g_qh);  cudaGetSymbolAddress((void**)&ql,  g_ql);
    cudaGetSymbolAddress((void**)&kh,  g_kh);  cudaGetSymbolAddress((void**)&kl,  g_kl);
    cudaGetSymbolAddress((void**)&vth, g_vth); cudaGetSymbolAddress((void**)&vtl, g_vtl);

    cudaFuncSetAttribute(gemm_hmma_kernel,
                         cudaFuncAttributeMaxDynamicSharedMemorySize, GEMM_SMEM);
    cudaFuncSetAttribute(attn_hmma_kernel,
                         cudaFuncAttributeMaxDynamicSharedMemorySize, AT_SMEM);

    const int T = 256;
    split_kernel<<<(SEQ * DIM / 4 + T - 1) / T, T>>>(x,  xh,  xl,  SEQ * DIM / 4);
    split_kernel<<<(DIM * DIM / 4 + T - 1) / T, T>>>(wq, wqh, wql, DIM * DIM / 4);
    split_kernel<<<(KVDIM * DIM / 4 + T - 1) / T, T>>>(wk, wkh, wkl, KVDIM * DIM / 4);
    split_kernel<<<(KVDIM * DIM / 4 + T - 1) / T, T>>>(wv, wvh, wvl, KVDIM * DIM / 4);
    split_kernel<<<(DIM * DIM / 4 + T - 1) / T, T>>>(wo, woh, wol, DIM * DIM / 4);

    // QKV projections (HMMA)
    gemm_hmma_kernel<<<dim3(DIM / 128,   SEQ / 128), 256, GEMM_SMEM>>>(
        xh, xl, wqh, wql, Q,  DIM);
    gemm_hmma_kernel<<<dim3(KVDIM / 128, SEQ / 128), 256, GEMM_SMEM>>>(
        xh, xl, wkh, wkl, Kp, KVDIM);
    gemm_hmma_kernel<<<dim3(KVDIM / 128, SEQ / 128), 256, GEMM_SMEM>>>(
        xh, xl, wvh, wvl, Vp, KVDIM);

    // RoPE + split (scale folded into Q); V transpose + split
    const float scale = 0.08838834764831845f;
    rope_split_kernel<<<(SEQ * NH  * 64 + T - 1) / T, T>>>(
        Q,  fc, qh, ql, NH,  scale, SEQ * NH  * 64);
    rope_split_kernel<<<(SEQ * NKV * 64 + T - 1) / T, T>>>(
        Kp, fc, kh, kl, NKV, 1.0f,  SEQ * NKV * 64);
    split_vt_kernel<<<(KVDIM * SEQ + T - 1) / T, T>>>(Vp, vth, vtl);

    // Attention (HMMA flash)
    attn_hmma_kernel<<<dim3(SEQ / 64, NH), 128, AT_SMEM>>>(
        qh, ql, kh, kl, vth, vtl, Yp);

    // Output projection
    split_kernel<<<(SEQ * DIM / 4 + T - 1) / T, T>>>(Yp, yh, yl, SEQ * DIM / 4);
    gemm_hmma_kernel<<<dim3(DIM / 128, SEQ / 128), 256, GEMM_SMEM>>>(
        yh, yl, woh, wol, out, DIM);
}

// round 5
// speedup vs baseline: 2.8905x; 1.0353x over previous
#include <cuda_runtime.h>
#include <cuda_bf16.h>
#include <math.h>
#include <stdint.h>

#define SEQ    2048
#define DIM    4096
#define NH     32
#define NKV    8
#define HD     128
#define KVDIM  (NKV*HD)

// ---------------------------------------------------------------------------
// Scratch (device globals; no allocation allowed)
// ---------------------------------------------------------------------------
static __device__ float g_q[SEQ * DIM];
static __device__ float g_k[SEQ * KVDIM];
static __device__ float g_v[SEQ * KVDIM];
static __device__ float g_y[SEQ * DIM];

static __device__ __nv_bfloat16 g_xh[SEQ * DIM],    g_xl[SEQ * DIM];
static __device__ __nv_bfloat16 g_wqh[DIM * DIM],   g_wql[DIM * DIM];
static __device__ __nv_bfloat16 g_wkh[KVDIM * DIM], g_wkl[KVDIM * DIM];
static __device__ __nv_bfloat16 g_wvh[KVDIM * DIM], g_wvl[KVDIM * DIM];
static __device__ __nv_bfloat16 g_woh[DIM * DIM],   g_wol[DIM * DIM];
static __device__ __nv_bfloat16 g_yh[SEQ * DIM],    g_yl[SEQ * DIM];

static __device__ __nv_bfloat16 g_qh[SEQ * DIM],    g_ql[SEQ * DIM];
static __device__ __nv_bfloat16 g_kh[SEQ * KVDIM],  g_kl[SEQ * KVDIM];
static __device__ __nv_bfloat16 g_vth[KVDIM * SEQ], g_vtl[KVDIM * SEQ];

// ---------------------------------------------------------------------------
// Helpers
// ---------------------------------------------------------------------------
__device__ __forceinline__ uint32_t smem_u32(const void* p) {
    uint32_t a;
    asm("{ .reg .u64 t; cvta.to.shared.u64 t, %1; cvt.u32.u64 %0, t; }"
        : "=r"(a) : "l"(p));
    return a;
}

__device__ __forceinline__ void ldsm_x4(uint32_t* d, uint32_t addr) {
    asm volatile("ldmatrix.sync.aligned.m8n8.x4.shared.b16 {%0,%1,%2,%3}, [%4];"
                 : "=r"(d[0]), "=r"(d[1]), "=r"(d[2]), "=r"(d[3]) : "r"(addr));
}

__device__ __forceinline__ void mma16816(float* c, const uint32_t* a,
                                         uint32_t b0, uint32_t b1) {
    asm volatile(
        "mma.sync.aligned.m16n8k16.row.col.f32.bf16.bf16.f32 "
        "{%0,%1,%2,%3}, {%4,%5,%6,%7}, {%8,%9}, {%0,%1,%2,%3};"
        : "+f"(c[0]), "+f"(c[1]), "+f"(c[2]), "+f"(c[3])
        : "r"(a[0]), "r"(a[1]), "r"(a[2]), "r"(a[3]), "r"(b0), "r"(b1));
}

#define CP_ASYNC16(dst, src) \
    asm volatile("cp.async.cg.shared.global [%0], [%1], 16;" :: "r"(dst), "l"(src))
#define CP_COMMIT() asm volatile("cp.async.commit_group;" ::: "memory")
#define CP_WAIT0()  asm volatile("cp.async.wait_group 0;"  ::: "memory")
#define CP_WAIT1()  asm volatile("cp.async.wait_group 1;"  ::: "memory")

__device__ __forceinline__ void split2(float a, __nv_bfloat16& h, __nv_bfloat16& l) {
    h = __float2bfloat16(a);
    l = __float2bfloat16(a - __bfloat162float(h));
}

// ---------------------------------------------------------------------------
// Split fp32 -> (bf16 hi, bf16 lo); 8 elements per thread.
// ---------------------------------------------------------------------------
__global__ void split_kernel(const float* __restrict__ in,
                             __nv_bfloat16* __restrict__ hi,
                             __nv_bfloat16* __restrict__ lo, int n8)
{
    int i = blockIdx.x * blockDim.x + threadIdx.x;
    if (i >= n8) return;
#pragma unroll
    for (int half = 0; half < 2; half++) {
        float4 v = ((const float4*)in)[2 * i + half];
        __nv_bfloat16 h0, h1, h2, h3, l0, l1, l2, l3;
        split2(v.x, h0, l0); split2(v.y, h1, l1);
        split2(v.z, h2, l2); split2(v.w, h3, l3);
        __nv_bfloat162* hp = (__nv_bfloat162*)hi;
        __nv_bfloat162* lp = (__nv_bfloat162*)lo;
        hp[4 * i + 2 * half]     = __nv_bfloat162(h0, h1);
        hp[4 * i + 2 * half + 1] = __nv_bfloat162(h2, h3);
        lp[4 * i + 2 * half]     = __nv_bfloat162(l0, l1);
        lp[4 * i + 2 * half + 1] = __nv_bfloat162(l2, l3);
    }
}

// ---------------------------------------------------------------------------
// RoPE + scale + split.  x: [SEQ, nheads, 128] fp32.
// ---------------------------------------------------------------------------
__global__ void rope_split_kernel(const float* __restrict__ x,
                                  const float* __restrict__ fc,
                                  __nv_bfloat16* __restrict__ oh,
                                  __nv_bfloat16* __restrict__ ol,
                                  int nheads, float scale, int total)
{
    int idx = blockIdx.x * blockDim.x + threadIdx.x;
    if (idx >= total) return;
    const int i = idx & 63;
    const int h = (idx >> 6) % nheads;
    const int s = idx / (64 * nheads);
    const float c  = fc[(s * 64 + i) * 2 + 0];
    const float sn = fc[(s * 64 + i) * 2 + 1];
    const size_t off = ((size_t)s * nheads + h) * HD + 2 * i;
    float2 v = *(const float2*)(x + off);
    float a = (v.x * c - v.y * sn) * scale;
    float b = (v.y * c + v.x * sn) * scale;
    __nv_bfloat16 ah, al, bh, bl;
    split2(a, ah, al); split2(b, bh, bl);
    *(__nv_bfloat162*)(oh + off) = __nv_bfloat162(ah, bh);
    *(__nv_bfloat162*)(ol + off) = __nv_bfloat162(al, bl);
}

// ---------------------------------------------------------------------------
// V transpose + split: [s][dl] -> [dl][s]
// ---------------------------------------------------------------------------
__global__ void split_vt_kernel(const float* __restrict__ v,
                                __nv_bfloat16* __restrict__ vh,
                                __nv_bfloat16* __restrict__ vl)
{
    int idx = blockIdx.x * blockDim.x + threadIdx.x;
    const int s = idx & (SEQ - 1);
    const int dl = idx >> 11;
    if (dl >= KVDIM) return;
    float val = v[(size_t)s * KVDIM + dl];
    __nv_bfloat16 h, l;
    split2(val, h, l);
    vh[idx] = h; vl[idx] = l;
}

// ---------------------------------------------------------------------------
// HMMA GEMM body. CTA tile 128x128, 8 warps, K=4096, K-chunk 32,
// 3-stage cp.async pipeline, one barrier per chunk.
// ---------------------------------------------------------------------------
#define GEMM_STAGE  32768
#define GEMM_SMEM   (3 * GEMM_STAGE + 1024)
#define GEMM_NC     (DIM / 32)

__device__ __forceinline__ void stage_load(
    uint32_t s_stage,
    const __nv_bfloat16* __restrict__ Ah, const __nv_bfloat16* __restrict__ Al,
    const __nv_bfloat16* __restrict__ Bh, const __nv_bfloat16* __restrict__ Bl,
    int row0, int col0, int k0, int tid)
{
    const int r  = tid >> 1;
    const int h  = tid & 1;
    const int sw = r & 7;
    const __nv_bfloat16* asrc = (h ? Al : Ah) + (size_t)(row0 + r) * DIM + k0;
    const __nv_bfloat16* bsrc = (h ? Bl : Bh) + (size_t)(col0 + r) * DIM + k0;
    const uint32_t arow = s_stage + r * 128;
    const uint32_t brow = s_stage + 16384 + r * 128;
#pragma unroll
    for (int u = 0; u < 4; u++) {
        const int phys = ((h * 4 + u) ^ sw) * 16;
        CP_ASYNC16(arow + phys, asrc + u * 8);
        CP_ASYNC16(brow + phys, bsrc + u * 8);
    }
}

__device__ __forceinline__ void gemm_body(
    const __nv_bfloat16* __restrict__ Ah, const __nv_bfloat16* __restrict__ Al,
    const __nv_bfloat16* __restrict__ Bh, const __nv_bfloat16* __restrict__ Bl,
    float* __restrict__ C, int Ntot, int row0, int col0, char* smraw)
{
    const uint32_t sbase = (smem_u32(smraw) + 1023u) & ~1023u;
    const int tid = threadIdx.x;
    const int lid = tid & 31;
    const int wid = tid >> 5;
    const int wm  = wid & 1;
    const int wn  = wid >> 1;

    float acc[4][4][4];
#pragma unroll
    for (int i = 0; i < 4; i++)
#pragma unroll
        for (int j = 0; j < 4; j++)
#pragma unroll
            for (int q = 0; q < 4; q++) acc[i][j][q] = 0.f;

    stage_load(sbase,              Ah, Al, Bh, Bl, row0, col0, 0,  tid);
    CP_COMMIT();
    stage_load(sbase + GEMM_STAGE, Ah, Al, Bh, Bl, row0, col0, 32, tid);
    CP_COMMIT();

    int cur = 0, nxt = 2;
    for (int c = 0; c < GEMM_NC; c++) {
        CP_WAIT1();
        __syncthreads();
        if (c + 2 < GEMM_NC) {
            stage_load(sbase + nxt * GEMM_STAGE,
                       Ah, Al, Bh, Bl, row0, col0, (c + 2) * 32, tid);
            CP_COMMIT();
        }
        const uint32_t aBase = sbase + cur * GEMM_STAGE;
        const uint32_t bBase = aBase + 16384;
        cur = (cur == 2) ? 0 : cur + 1;
        nxt = (nxt == 2) ? 0 : nxt + 1;

#pragma unroll
        for (int ks = 0; ks < 2; ks++) {
            uint32_t ah[4][4], bh[2][4], bl[2][4];
#pragma unroll
            for (int mt = 0; mt < 4; mt++) {
                const int r = wm * 64 + mt * 16 + (lid & 15);
                const int lu = ks * 2 + (lid >> 4);
                ldsm_x4(ah[mt], aBase + r * 128 + ((lu ^ (r & 7)) * 16));
            }
#pragma unroll
            for (int np = 0; np < 2; np++) {
                const int r  = wn * 32 + np * 16 + ((lid >> 4) & 1) * 8 + (lid & 7);
                const int lu = ks * 2 + ((lid >> 3) & 1);
                ldsm_x4(bh[np], bBase + r * 128 + ((lu ^ (r & 7)) * 16));
                ldsm_x4(bl[np], bBase + r * 128 + (((lu + 4) ^ (r & 7)) * 16));
            }
#pragma unroll
            for (int mt = 0; mt < 4; mt++)
#pragma unroll
                for (int nt = 0; nt < 4; nt++) {
                    mma16816(acc[mt][nt], ah[mt],
                             bh[nt >> 1][(nt & 1) * 2], bh[nt >> 1][(nt & 1) * 2 + 1]);
                    mma16816(acc[mt][nt], ah[mt],
                             bl[nt >> 1][(nt & 1) * 2], bl[nt >> 1][(nt & 1) * 2 + 1]);
                }
#pragma unroll
            for (int mt = 0; mt < 4; mt++) {
                const int r = wm * 64 + mt * 16 + (lid & 15);
                const int lu = 4 + ks * 2 + (lid >> 4);
                ldsm_x4(ah[mt], aBase + r * 128 + ((lu ^ (r & 7)) * 16));
            }
#pragma unroll
            for (int mt = 0; mt < 4; mt++)
#pragma unroll
                for (int nt = 0; nt < 4; nt++)
                    mma16816(acc[mt][nt], ah[mt],
                             bh[nt >> 1][(nt & 1) * 2], bh[nt >> 1][(nt & 1) * 2 + 1]);
        }
    }

#pragma unroll
    for (int mt = 0; mt < 4; mt++) {
        const int r = row0 + wm * 64 + mt * 16 + (lid >> 2);
#pragma unroll
        for (int nt = 0; nt < 4; nt++) {
            const int cc = col0 + wn * 32 + nt * 8 + (lid & 3) * 2;
            *(float2*)&C[(size_t)r * Ntot + cc] =
                make_float2(acc[mt][nt][0], acc[mt][nt][1]);
            *(float2*)&C[(size_t)(r + 8) * Ntot + cc] =
                make_float2(acc[mt][nt][2], acc[mt][nt][3]);
        }
    }
}

// Fused QKV: blockIdx.x 0..47  (0-31 Q, 32-39 K, 40-47 V)
__global__ void __launch_bounds__(256, 2)
gemm_qkv_kernel(const __nv_bfloat16* __restrict__ xh,
                const __nv_bfloat16* __restrict__ xl,
                const __nv_bfloat16* __restrict__ wqh, const __nv_bfloat16* __restrict__ wql,
                const __nv_bfloat16* __restrict__ wkh, const __nv_bfloat16* __restrict__ wkl,
                const __nv_bfloat16* __restrict__ wvh, const __nv_bfloat16* __restrict__ wvl,
                float* __restrict__ Q, float* __restrict__ K, float* __restrict__ V)
{
    extern __shared__ char smraw[];
    const int xb = blockIdx.x;
    const int row0 = blockIdx.y * 128;
    const __nv_bfloat16 *Bh, *Bl;
    float* C; int Ntot, col0;
    if (xb < 32)      { Bh = wqh; Bl = wql; C = Q; Ntot = DIM;   col0 = xb * 128; }
    else if (xb < 40) { Bh = wkh; Bl = wkl; C = K; Ntot = KVDIM; col0 = (xb - 32) * 128; }
    else              { Bh = wvh; Bl = wvl; C = V; Ntot = KVDIM; col0 = (xb - 40) * 128; }
    gemm_body(xh, xl, Bh, Bl, C, Ntot, row0, col0, smraw);
}

__global__ void __launch_bounds__(256, 2)
gemm_hmma_kernel(const __nv_bfloat16* __restrict__ Ah,
                 const __nv_bfloat16* __restrict__ Al,
                 const __nv_bfloat16* __restrict__ Bh,
                 const __nv_bfloat16* __restrict__ Bl,
                 float* __restrict__ C, int Ntot)
{
    extern __shared__ char smraw[];
    gemm_body(Ah, Al, Bh, Bl, C, Ntot, blockIdx.y * 128, blockIdx.x * 128, smraw);
}

// ---------------------------------------------------------------------------
// HMMA flash attention with split P and cp.async-pipelined KV.
// Br=64 (4 warps), Bc=64, causal, GQA rep 4.
// S = Qh.Kh + Qh.Kl + Ql.Kh;  O = Ph.Vh + Pl.Vh + Ph.Vl.
// smem: Qh 16K | Ql 16K | 2 stages x (Kh,Kl 16K each; Vh,Vl 16K each)
// ---------------------------------------------------------------------------
#define AT_QH 0
#define AT_QL 16384
#define AT_ST(b) (32768 + (b) * 65536)
#define AT_KH 0
#define AT_KL 16384
#define AT_VH 32768
#define AT_VL 49152
#define AT_SMEM (32768 + 2 * 65536)

__device__ __forceinline__ void attn_load_kv(
    uint32_t stage, const __nv_bfloat16* __restrict__ Kh,
    const __nv_bfloat16* __restrict__ Kl,
    const __nv_bfloat16* __restrict__ Vth, const __nv_bfloat16* __restrict__ Vtl,
    int j, int kvh, int tid)
{
    for (int idx = tid; idx < 1024; idx += 128) {
        const int r = idx >> 4, u = idx & 15;
        const int phys = ((u ^ (r & 7)) * 16);
        const size_t gk = ((size_t)(j * 64 + r) * NKV + kvh) * HD + u * 8;
        CP_ASYNC16(stage + AT_KH + r * 256 + phys, Kh + gk);
        CP_ASYNC16(stage + AT_KL + r * 256 + phys, Kl + gk);
    }
    for (int idx = tid; idx < 1024; idx += 128) {
        const int r = idx >> 3, u = idx & 7;
        const int phys = ((u ^ (r & 7)) * 16);
        const size_t gv = ((size_t)(kvh * 128 + r)) * SEQ + j * 64 + u * 8;
        CP_ASYNC16(stage + AT_VH + r * 128 + phys, Vth + gv);
        CP_ASYNC16(stage + AT_VL + r * 128 + phys, Vtl + gv);
    }
}

__global__ void __launch_bounds__(128)
attn_hmma_kernel(const __nv_bfloat16* __restrict__ Qh,
                 const __nv_bfloat16* __restrict__ Ql,
                 const __nv_bfloat16* __restrict__ Kh,
                 const __nv_bfloat16* __restrict__ Kl,
                 const __nv_bfloat16* __restrict__ Vth,
                 const __nv_bfloat16* __restrict__ Vtl,
                 float* __restrict__ Y)
{
    extern __shared__ char smraw[];
    const uint32_t sb = smem_u32(smraw);

    const int qt  = blockIdx.x;
    const int h   = blockIdx.y;
    const int kvh = h >> 2;
    const int tid = threadIdx.x;
    const int lid = tid & 31;
    const int wid = tid >> 5;
    const int qrow0 = qt * 64;

    // Q tile + KV(0) via cp.async (one group)
    for (int idx = tid; idx < 1024; idx += 128) {
        const int r = idx >> 4, u = idx & 15;
        const int phys = ((u ^ (r & 7)) * 16);
        const size_t g = ((size_t)(qrow0 + r) * NH + h) * HD + u * 8;
        CP_ASYNC16(sb + AT_QH + r * 256 + phys, Qh + g);
        CP_ASYNC16(sb + AT_QL + r * 256 + phys, Ql + g);
    }
    attn_load_kv(sb + AT_ST(0), Kh, Kl, Vth, Vtl, 0, kvh, tid);
    CP_COMMIT();

    float o[16][4];
#pragma unroll
    for (int dt = 0; dt < 16; dt++)
#pragma unroll
        for (int q = 0; q < 4; q++) o[dt][q] = 0.f;
    float mA = -1e30f, mB = -1e30f, lA = 0.f, lB = 0.f;

    const int g  = lid >> 2;
    const int cA = (lid & 3) * 2;

    for (int j = 0; j <= qt; j++) {
        CP_WAIT0();
        __syncthreads();
        if (j < qt) {
            attn_load_kv(sb + AT_ST((j + 1) & 1), Kh, Kl, Vth, Vtl, j + 1, kvh, tid);
            CP_COMMIT();
        }
        const uint32_t kb = sb + AT_ST(j & 1);

        // ---- S = Q K^T (split) ----
        float s[8][4];
#pragma unroll
        for (int nt = 0; nt < 8; nt++)
#pragma unroll
            for (int q = 0; q < 4; q++) s[nt][q] = 0.f;

#pragma unroll
        for (int kc = 0; kc < 8; kc++) {
            uint32_t qhf[4], qlf[4];
            const int rA = wid * 16 + (lid & 15);
            const int uA = kc * 2 + (lid >> 4);
            ldsm_x4(qhf, sb + AT_QH + rA * 256 + ((uA ^ (rA & 7)) * 16));
            ldsm_x4(qlf, sb + AT_QL + rA * 256 + ((uA ^ (rA & 7)) * 16));
#pragma unroll
            for (int np = 0; np < 4; np++) {
                uint32_t khf[4], klf[4];
                const int rB = np * 16 + ((lid >> 4) & 1) * 8 + (lid & 7);
                const int uB = kc * 2 + ((lid >> 3) & 1);
                ldsm_x4(khf, kb + AT_KH + rB * 256 + ((uB ^ (rB & 7)) * 16));
                ldsm_x4(klf, kb + AT_KL + rB * 256 + ((uB ^ (rB & 7)) * 16));
#pragma unroll
                for (int hf = 0; hf < 2; hf++) {
                    const int nt = np * 2 + hf;
                    mma16816(s[nt], qhf, khf[hf * 2], khf[hf * 2 + 1]);
                    mma16816(s[nt], qhf, klf[hf * 2], klf[hf * 2 + 1]);
                    mma16816(s[nt], qlf, khf[hf * 2], khf[hf * 2 + 1]);
                }
            }
        }

        // ---- causal mask on diagonal tile ----
        if (j == qt) {
            const int rowA = wid * 16 + g;
#pragma unroll
            for (int nt = 0; nt < 8; nt++) {
                const int col = nt * 8 + cA;
                if (col     > rowA)     s[nt][0] = -1e30f;
                if (col + 1 > rowA)     s[nt][1] = -1e30f;
                if (col     > rowA + 8) s[nt][2] = -1e30f;
                if (col + 1 > rowA + 8) s[nt][3] = -1e30f;
            }
        }

        // ---- online softmax (fp32 p, then split to Ph+Pl) ----
        float mxA = -1e30f, mxB = -1e30f;
#pragma unroll
        for (int nt = 0; nt < 8; nt++) {
            mxA = fmaxf(mxA, fmaxf(s[nt][0], s[nt][1]));
            mxB = fmaxf(mxB, fmaxf(s[nt][2], s[nt][3]));
        }
        mxA = fmaxf(mxA, __shfl_xor_sync(0xffffffffu, mxA, 1));
        mxA = fmaxf(mxA, __shfl_xor_sync(0xffffffffu, mxA, 2));
        mxB = fmaxf(mxB, __shfl_xor_sync(0xffffffffu, mxB, 1));
        mxB = fmaxf(mxB, __shfl_xor_sync(0xffffffffu, mxB, 2));
        const float mnA = fmaxf(mA, mxA), mnB = fmaxf(mB, mxB);
        const float alA = __expf(mA - mnA), alB = __expf(mB - mnB);

        uint32_t ph[8][2], pl[8][2];
        float rsA = 0.f, rsB = 0.f;
#pragma unroll
        for (int nt = 0; nt < 8; nt++) {
            float p0 = __expf(s[nt][0] - mnA);
            float p1 = __expf(s[nt][1] - mnA);
            float p2 = __expf(s[nt][2] - mnB);
            float p3 = __expf(s[nt][3] - mnB);
            rsA += p0 + p1;  rsB += p2 + p3;
            __nv_bfloat16 h0, h1, h2, h3, e0, e1, e2, e3;
            split2(p0, h0, e0); split2(p1, h1, e1);
            split2(p2, h2, e2); split2(p3, h3, e3);
            __nv_bfloat162 a0(h0, h1), a1(h2, h3), b0(e0, e1), b1(e2, e3);
            ph[nt][0] = *reinterpret_cast<uint32_t*>(&a0);
            ph[nt][1] = *reinterpret_cast<uint32_t*>(&a1);
            pl[nt][0] = *reinterpret_cast<uint32_t*>(&b0);
            pl[nt][1] = *reinterpret_cast<uint32_t*>(&b1);
        }
        rsA += __shfl_xor_sync(0xffffffffu, rsA, 1);
        rsA += __shfl_xor_sync(0xffffffffu, rsA, 2);
        rsB += __shfl_xor_sync(0xffffffffu, rsB, 1);
        rsB += __shfl_xor_sync(0xffffffffu, rsB, 2);
        lA = lA * alA + rsA;  mA = mnA;
        lB = lB * alB + rsB;  mB = mnB;

#pragma unroll
        for (int dt = 0; dt < 16; dt++) {
            o[dt][0] *= alA; o[dt][1] *= alA;
            o[dt][2] *= alB; o[dt][3] *= alB;
        }

        // ---- O += Ph.Vh + Pl.Vh + Ph.Vl ----
#pragma unroll
        for (int kc = 0; kc < 4; kc++) {
            uint32_t aH[4] = { ph[2 * kc][0], ph[2 * kc][1],
                               ph[2 * kc + 1][0], ph[2 * kc + 1][1] };
            uint32_t aL[4] = { pl[2 * kc][0], pl[2 * kc][1],
                               pl[2 * kc + 1][0], pl[2 * kc + 1][1] };
#pragma unroll
            for (int dp = 0; dp < 8; dp++) {
                uint32_t vhf[4], vlf[4];
                const int rB = dp * 16 + ((lid >> 4) & 1) * 8 + (lid & 7);
                const int uB = kc * 2 + ((lid >> 3) & 1);
                ldsm_x4(vhf, kb + AT_VH + rB * 128 + ((uB ^ (rB & 7)) * 16));
                ldsm_x4(vlf, kb + AT_VL + rB * 128 + ((uB ^ (rB & 7)) * 16));
#pragma unroll
                for (int hf = 0; hf < 2; hf++) {
                    const int dt = dp * 2 + hf;
                    mma16816(o[dt], aH, vhf[hf * 2], vhf[hf * 2 + 1]);
                    mma16816(o[dt], aL, vhf[hf * 2], vhf[hf * 2 + 1]);
                    mma16816(o[dt], aH, vlf[hf * 2], vlf[hf * 2 + 1]);
                }
            }
        }
    }

    // Epilogue
    const float invA = 1.f / lA, invB = 1.f / lB;
    const int rowA = qrow0 + wid * 16 + g;
#pragma unroll
    for (int dt = 0; dt < 16; dt++) {
        const int d = h * HD + dt * 8 + cA;
        *(float2*)&Y[(size_t)rowA * DIM + d] =
            make_float2(o[dt][0] * invA, o[dt][1] * invA);
        *(float2*)&Y[(size_t)(rowA + 8) * DIM + d] =
            make_float2(o[dt][2] * invB, o[dt][3] * invB);
    }
}

// ---------------------------------------------------------------------------
// Launch
// ---------------------------------------------------------------------------
extern "C" void kernel_launch(void* const* d_in, const int* in_sizes, int n_in,
                              void* d_out, int out_size)
{
    const float* x  = (const float*)d_in[0];
    const float* fc = (const float*)d_in[1];
    const float* wq = (const float*)d_in[3];
    const float* wk = (const float*)d_in[4];
    const float* wv = (const float*)d_in[5];
    const float* wo = (const float*)d_in[6];
    float* out = (float*)d_out;

    float *Q, *Kp, *Vp, *Yp;
    cudaGetSymbolAddress((void**)&Q,  g_q);
    cudaGetSymbolAddress((void**)&Kp, g_k);
    cudaGetSymbolAddress((void**)&Vp, g_v);
    cudaGetSymbolAddress((void**)&Yp, g_y);

    __nv_bfloat16 *xh, *xl, *wqh, *wql, *wkh, *wkl, *wvh, *wvl, *woh, *wol, *yh, *yl;
    __nv_bfloat16 *qh, *ql, *kh, *kl, *vth, *vtl;
    cudaGetSymbolAddress((void**)&xh,  g_xh);  cudaGetSymbolAddress((void**)&xl,  g_xl);
    cudaGetSymbolAddress((void**)&wqh, g_wqh); cudaGetSymbolAddress((void**)&wql, g_wql);
    cudaGetSymbolAddress((void**)&wkh, g_wkh); cudaGetSymbolAddress((void**)&wkl, g_wkl);
    cudaGetSymbolAddress((void**)&wvh, g_wvh); cudaGetSymbolAddress((void**)&wvl, g_wvl);
    cudaGetSymbolAddress((void**)&woh, g_woh); cudaGetSymbolAddress((void**)&wol, g_wol);
    cudaGetSymbolAddress((void**)&yh,  g_yh);  cudaGetSymbolAddress((void**)&yl,  g_yl);
    cudaGetSymbolAddress((void**)&qh,  g_qh);  cudaGetSymbolAddress((void**)&ql,  g_ql);
    cudaGetSymbolAddress((void**)&kh,  g_kh);  cudaGetSymbolAddress((void**)&kl,  g_kl);
    cudaGetSymbolAddress((void**)&vth, g_vth); cudaGetSymbolAddress((void**)&vtl, g_vtl);

    cudaFuncSetAttribute(gemm_qkv_kernel,
                         cudaFuncAttributeMaxDynamicSharedMemorySize, GEMM_SMEM);
    cudaFuncSetAttribute(gemm_hmma_kernel,
                         cudaFuncAttributeMaxDynamicSharedMemorySize, GEMM_SMEM);
    cudaFuncSetAttribute(attn_hmma_kernel,
                         cudaFuncAttributeMaxDynamicSharedMemorySize, AT_SMEM);

    const int T = 256;
    split_kernel<<<(SEQ * DIM / 8 + T - 1) / T, T>>>(x,  xh,  xl,  SEQ * DIM / 8);
    split_kernel<<<(DIM * DIM / 8 + T - 1) / T, T>>>(wq, wqh, wql, DIM * DIM / 8);
    split_kernel<<<(KVDIM * DIM / 8 + T - 1) / T, T>>>(wk, wkh, wkl, KVDIM * DIM / 8);
    split_kernel<<<(KVDIM * DIM / 8 + T - 1) / T, T>>>(wv, wvh, wvl, KVDIM * DIM / 8);
    split_kernel<<<(DIM * DIM / 8 + T - 1) / T, T>>>(wo, woh, wol, DIM * DIM / 8);

    // Fused QKV projection
    gemm_qkv_kernel<<<dim3(48, SEQ / 128), 256, GEMM_SMEM>>>(
        xh, xl, wqh, wql, wkh, wkl, wvh, wvl, Q, Kp, Vp);

    // RoPE + split; V transpose + split
    const float scale = 0.08838834764831845f;
    rope_split_kernel<<<(SEQ * NH  * 64 + T - 1) / T, T>>>(
        Q,  fc, qh, ql, NH,  scale, SEQ * NH  * 64);
    rope_split_kernel<<<(SEQ * NKV * 64 + T - 1) / T, T>>>(
        Kp, fc, kh, kl, NKV, 1.0f,  SEQ * NKV * 64);
    split_vt_kernel<<<(KVDIM * SEQ + T - 1) / T, T>>>(Vp, vth, vtl);

    // Attention
    attn_hmma_kernel<<<dim3(SEQ / 64, NH), 128, AT_SMEM>>>(
        qh, ql, kh, kl, vth, vtl, Yp);

    // Output projection
    split_kernel<<<(SEQ * DIM / 8 + T - 1) / T, T>>>(Yp, yh, yl, SEQ * DIM / 8);
    gemm_hmma_kernel<<<dim3(DIM / 128, SEQ / 128), 256, GEMM_SMEM>>>(
        yh, yl, woh, wol, out, DIM);
}

// round 6
// speedup vs baseline: 2.9853x; 1.0328x over previous
#include <cuda_runtime.h>
#include <cuda_bf16.h>
#include <math.h>
#include <stdint.h>

#define SEQ    2048
#define DIM    4096
#define NH     32
#define NKV    8
#define HD     128
#define KVDIM  (NKV*HD)

// ---------------------------------------------------------------------------
// Scratch (device globals)
// ---------------------------------------------------------------------------
static __device__ float g_q[SEQ * DIM];
static __device__ float g_k[SEQ * KVDIM];
static __device__ float g_v[SEQ * KVDIM];
static __device__ float g_y[SEQ * DIM];

static __device__ __nv_bfloat16 g_xh[SEQ * DIM],    g_xl[SEQ * DIM];
static __device__ __nv_bfloat16 g_wqh[DIM * DIM],   g_wql[DIM * DIM];
static __device__ __nv_bfloat16 g_wkh[KVDIM * DIM], g_wkl[KVDIM * DIM];
static __device__ __nv_bfloat16 g_wvh[KVDIM * DIM], g_wvl[KVDIM * DIM];
static __device__ __nv_bfloat16 g_woh[DIM * DIM],   g_wol[DIM * DIM];
static __device__ __nv_bfloat16 g_yh[SEQ * DIM],    g_yl[SEQ * DIM];

static __device__ __nv_bfloat16 g_qh[SEQ * DIM],    g_ql[SEQ * DIM];
static __device__ __nv_bfloat16 g_kh[SEQ * KVDIM],  g_kl[SEQ * KVDIM];
static __device__ __nv_bfloat16 g_vth[KVDIM * SEQ], g_vtl[KVDIM * SEQ];

// ---------------------------------------------------------------------------
// Helpers
// ---------------------------------------------------------------------------
__device__ __forceinline__ uint32_t smem_u32(const void* p) {
    uint32_t a;
    asm("{ .reg .u64 t; cvta.to.shared.u64 t, %1; cvt.u32.u64 %0, t; }"
        : "=r"(a) : "l"(p));
    return a;
}

__device__ __forceinline__ void ldsm_x4(uint32_t* d, uint32_t addr) {
    asm volatile("ldmatrix.sync.aligned.m8n8.x4.shared.b16 {%0,%1,%2,%3}, [%4];"
                 : "=r"(d[0]), "=r"(d[1]), "=r"(d[2]), "=r"(d[3]) : "r"(addr));
}

__device__ __forceinline__ void mma16816(float* c, const uint32_t* a,
                                         uint32_t b0, uint32_t b1) {
    asm volatile(
        "mma.sync.aligned.m16n8k16.row.col.f32.bf16.bf16.f32 "
        "{%0,%1,%2,%3}, {%4,%5,%6,%7}, {%8,%9}, {%0,%1,%2,%3};"
        : "+f"(c[0]), "+f"(c[1]), "+f"(c[2]), "+f"(c[3])
        : "r"(a[0]), "r"(a[1]), "r"(a[2]), "r"(a[3]), "r"(b0), "r"(b1));
}

#define CP_ASYNC16(dst, src) \
    asm volatile("cp.async.cg.shared.global [%0], [%1], 16;" :: "r"(dst), "l"(src))
#define CP_COMMIT() asm volatile("cp.async.commit_group;" ::: "memory")
#define CP_WAIT0()  asm volatile("cp.async.wait_group 0;"  ::: "memory")
#define CP_WAIT1()  asm volatile("cp.async.wait_group 1;"  ::: "memory")

__device__ __forceinline__ void split2(float a, __nv_bfloat16& h, __nv_bfloat16& l) {
    h = __float2bfloat16(a);
    l = __float2bfloat16(a - __bfloat162float(h));
}

// ---------------------------------------------------------------------------
// Pointwise kernels
// ---------------------------------------------------------------------------
__global__ void split_kernel(const float* __restrict__ in,
                             __nv_bfloat16* __restrict__ hi,
                             __nv_bfloat16* __restrict__ lo, int n8)
{
    int i = blockIdx.x * blockDim.x + threadIdx.x;
    if (i >= n8) return;
#pragma unroll
    for (int half = 0; half < 2; half++) {
        float4 v = ((const float4*)in)[2 * i + half];
        __nv_bfloat16 h0, h1, h2, h3, l0, l1, l2, l3;
        split2(v.x, h0, l0); split2(v.y, h1, l1);
        split2(v.z, h2, l2); split2(v.w, h3, l3);
        __nv_bfloat162* hp = (__nv_bfloat162*)hi;
        __nv_bfloat162* lp = (__nv_bfloat162*)lo;
        hp[4 * i + 2 * half]     = __nv_bfloat162(h0, h1);
        hp[4 * i + 2 * half + 1] = __nv_bfloat162(h2, h3);
        lp[4 * i + 2 * half]     = __nv_bfloat162(l0, l1);
        lp[4 * i + 2 * half + 1] = __nv_bfloat162(l2, l3);
    }
}

__global__ void rope_split_kernel(const float* __restrict__ x,
                                  const float* __restrict__ fc,
                                  __nv_bfloat16* __restrict__ oh,
                                  __nv_bfloat16* __restrict__ ol,
                                  int nheads, float scale, int total)
{
    int idx = blockIdx.x * blockDim.x + threadIdx.x;
    if (idx >= total) return;
    const int i = idx & 63;
    const int h = (idx >> 6) % nheads;
    const int s = idx / (64 * nheads);
    const float c  = fc[(s * 64 + i) * 2 + 0];
    const float sn = fc[(s * 64 + i) * 2 + 1];
    const size_t off = ((size_t)s * nheads + h) * HD + 2 * i;
    float2 v = *(const float2*)(x + off);
    float a = (v.x * c - v.y * sn) * scale;
    float b = (v.y * c + v.x * sn) * scale;
    __nv_bfloat16 ah, al, bh, bl;
    split2(a, ah, al); split2(b, bh, bl);
    *(__nv_bfloat162*)(oh + off) = __nv_bfloat162(ah, bh);
    *(__nv_bfloat162*)(ol + off) = __nv_bfloat162(al, bl);
}

__global__ void split_vt_kernel(const float* __restrict__ v,
                                __nv_bfloat16* __restrict__ vh,
                                __nv_bfloat16* __restrict__ vl)
{
    int idx = blockIdx.x * blockDim.x + threadIdx.x;
    const int s = idx & (SEQ - 1);
    const int dl = idx >> 11;
    if (dl >= KVDIM) return;
    float val = v[(size_t)s * KVDIM + dl];
    __nv_bfloat16 h, l;
    split2(val, h, l);
    vh[idx] = h; vl[idx] = l;
}

// ---------------------------------------------------------------------------
// HMMA GEMM. CTA tile 128x256, 8 warps (2x4), warp tile 64x64, K-chunk 32,
// 3-stage cp.async.  Stage: A 16KB (128 rows x 128B) + B 32KB (256 rows x 128B).
// Row layout: [hi 32 bf16 | lo 32 bf16], SW128 swizzle on 16B units.
// ---------------------------------------------------------------------------
#define GEMM_STAGE  49152
#define GEMM_SMEM   (3 * GEMM_STAGE + 1024)
#define GEMM_NC     (DIM / 32)

__device__ __forceinline__ void stage_load(
    uint32_t s_stage,
    const __nv_bfloat16* __restrict__ Ah, const __nv_bfloat16* __restrict__ Al,
    const __nv_bfloat16* __restrict__ Bh, const __nv_bfloat16* __restrict__ Bl,
    int row0, int col0, int k0, int tid)
{
    const int r  = tid >> 1;
    const int h  = tid & 1;
    const int sw = r & 7;
    // A: 128 rows
    {
        const __nv_bfloat16* src = (h ? Al : Ah) + (size_t)(row0 + r) * DIM + k0;
        const uint32_t rowp = s_stage + r * 128;
#pragma unroll
        for (int u = 0; u < 4; u++)
            CP_ASYNC16(rowp + (((h * 4 + u) ^ sw) * 16), src + u * 8);
    }
    // B: 256 rows, two passes
#pragma unroll
    for (int p = 0; p < 2; p++) {
        const int rb = r + p * 128;
        const int swb = rb & 7;
        const __nv_bfloat16* src = (h ? Bl : Bh) + (size_t)(col0 + rb) * DIM + k0;
        const uint32_t rowp = s_stage + 16384 + rb * 128;
#pragma unroll
        for (int u = 0; u < 4; u++)
            CP_ASYNC16(rowp + (((h * 4 + u) ^ swb) * 16), src + u * 8);
    }
}

__device__ __forceinline__ void gemm_body(
    const __nv_bfloat16* __restrict__ Ah, const __nv_bfloat16* __restrict__ Al,
    const __nv_bfloat16* __restrict__ Bh, const __nv_bfloat16* __restrict__ Bl,
    float* __restrict__ C, int Ntot, int row0, int col0, char* smraw)
{
    const uint32_t sbase = (smem_u32(smraw) + 1023u) & ~1023u;
    const int tid = threadIdx.x;
    const int lid = tid & 31;
    const int wid = tid >> 5;
    const int wm  = wid & 1;        // 2 in M
    const int wn  = wid >> 1;       // 4 in N

    float acc[4][8][4];
#pragma unroll
    for (int i = 0; i < 4; i++)
#pragma unroll
        for (int j = 0; j < 8; j++)
#pragma unroll
            for (int q = 0; q < 4; q++) acc[i][j][q] = 0.f;

    stage_load(sbase,              Ah, Al, Bh, Bl, row0, col0, 0,  tid);
    CP_COMMIT();
    stage_load(sbase + GEMM_STAGE, Ah, Al, Bh, Bl, row0, col0, 32, tid);
    CP_COMMIT();

    int cur = 0, nxt = 2;
    for (int c = 0; c < GEMM_NC; c++) {
        CP_WAIT1();
        __syncthreads();
        if (c + 2 < GEMM_NC) {
            stage_load(sbase + nxt * GEMM_STAGE,
                       Ah, Al, Bh, Bl, row0, col0, (c + 2) * 32, tid);
            CP_COMMIT();
        }
        const uint32_t aBase = sbase + cur * GEMM_STAGE;
        const uint32_t bBase = aBase + 16384;
        cur = (cur == 2) ? 0 : cur + 1;
        nxt = (nxt == 2) ? 0 : nxt + 1;

#pragma unroll
        for (int ks = 0; ks < 2; ks++) {
            uint32_t af[4][4], bhf[4][4], blf[4][4];
#pragma unroll
            for (int mt = 0; mt < 4; mt++) {
                const int r = wm * 64 + mt * 16 + (lid & 15);
                const int lu = ks * 2 + (lid >> 4);
                ldsm_x4(af[mt], aBase + r * 128 + ((lu ^ (r & 7)) * 16));
            }
#pragma unroll
            for (int np = 0; np < 4; np++) {
                const int r  = wn * 64 + np * 16 + ((lid >> 4) & 1) * 8 + (lid & 7);
                const int lu = ks * 2 + ((lid >> 3) & 1);
                ldsm_x4(bhf[np], bBase + r * 128 + ((lu ^ (r & 7)) * 16));
                ldsm_x4(blf[np], bBase + r * 128 + (((lu + 4) ^ (r & 7)) * 16));
            }
            // Ah*Bh + Ah*Bl
#pragma unroll
            for (int mt = 0; mt < 4; mt++)
#pragma unroll
                for (int nt = 0; nt < 8; nt++) {
                    mma16816(acc[mt][nt], af[mt],
                             bhf[nt >> 1][(nt & 1) * 2], bhf[nt >> 1][(nt & 1) * 2 + 1]);
                    mma16816(acc[mt][nt], af[mt],
                             blf[nt >> 1][(nt & 1) * 2], blf[nt >> 1][(nt & 1) * 2 + 1]);
                }
            // Al*Bh
#pragma unroll
            for (int mt = 0; mt < 4; mt++) {
                const int r = wm * 64 + mt * 16 + (lid & 15);
                const int lu = 4 + ks * 2 + (lid >> 4);
                ldsm_x4(af[mt], aBase + r * 128 + ((lu ^ (r & 7)) * 16));
            }
#pragma unroll
            for (int mt = 0; mt < 4; mt++)
#pragma unroll
                for (int nt = 0; nt < 8; nt++)
                    mma16816(acc[mt][nt], af[mt],
                             bhf[nt >> 1][(nt & 1) * 2], bhf[nt >> 1][(nt & 1) * 2 + 1]);
        }
    }

#pragma unroll
    for (int mt = 0; mt < 4; mt++) {
        const int r = row0 + wm * 64 + mt * 16 + (lid >> 2);
#pragma unroll
        for (int nt = 0; nt < 8; nt++) {
            const int cc = col0 + wn * 64 + nt * 8 + (lid & 3) * 2;
            *(float2*)&C[(size_t)r * Ntot + cc] =
                make_float2(acc[mt][nt][0], acc[mt][nt][1]);
            *(float2*)&C[(size_t)(r + 8) * Ntot + cc] =
                make_float2(acc[mt][nt][2], acc[mt][nt][3]);
        }
    }
}

// Fused QKV: blockIdx.x 0..23  (0-15 Q, 16-19 K, 20-23 V)
__global__ void __launch_bounds__(256, 1)
gemm_qkv_kernel(const __nv_bfloat16* __restrict__ xh,
                const __nv_bfloat16* __restrict__ xl,
                const __nv_bfloat16* __restrict__ wqh, const __nv_bfloat16* __restrict__ wql,
                const __nv_bfloat16* __restrict__ wkh, const __nv_bfloat16* __restrict__ wkl,
                const __nv_bfloat16* __restrict__ wvh, const __nv_bfloat16* __restrict__ wvl,
                float* __restrict__ Q, float* __restrict__ K, float* __restrict__ V)
{
    extern __shared__ char smraw[];
    const int xb = blockIdx.x;
    const int row0 = blockIdx.y * 128;
    const __nv_bfloat16 *Bh, *Bl;
    float* C; int Ntot, col0;
    if (xb < 16)      { Bh = wqh; Bl = wql; C = Q; Ntot = DIM;   col0 = xb * 256; }
    else if (xb < 20) { Bh = wkh; Bl = wkl; C = K; Ntot = KVDIM; col0 = (xb - 16) * 256; }
    else              { Bh = wvh; Bl = wvl; C = V; Ntot = KVDIM; col0 = (xb - 20) * 256; }
    gemm_body(xh, xl, Bh, Bl, C, Ntot, row0, col0, smraw);
}

__global__ void __launch_bounds__(256, 1)
gemm_hmma_kernel(const __nv_bfloat16* __restrict__ Ah,
                 const __nv_bfloat16* __restrict__ Al,
                 const __nv_bfloat16* __restrict__ Bh,
                 const __nv_bfloat16* __restrict__ Bl,
                 float* __restrict__ C, int Ntot)
{
    extern __shared__ char smraw[];
    gemm_body(Ah, Al, Bh, Bl, C, Ntot, blockIdx.y * 128, blockIdx.x * 256, smraw);
}

// ---------------------------------------------------------------------------
// HMMA flash attention. Br=128 (8 warps x m16), Bc=64, causal, GQA rep 4.
// S = Qh.Kh + Qh.Kl + Ql.Kh;  O = Ph.Vh + Pl.Vh + Ph.Vl.
// smem: Qh 32K | Ql 32K | 2 stages x (Kh,Kl 16K; Vh,Vl 16K) = 192KB.
// ---------------------------------------------------------------------------
#define AT_QH 0
#define AT_QL 32768
#define AT_ST(b) (65536 + (b) * 65536)
#define AT_KH 0
#define AT_KL 16384
#define AT_VH 32768
#define AT_VL 49152
#define AT_SMEM (65536 + 2 * 65536)

__device__ __forceinline__ void attn_load_kv(
    uint32_t stage, const __nv_bfloat16* __restrict__ Kh,
    const __nv_bfloat16* __restrict__ Kl,
    const __nv_bfloat16* __restrict__ Vth, const __nv_bfloat16* __restrict__ Vtl,
    int j, int kvh, int tid)
{
    for (int idx = tid; idx < 1024; idx += 256) {
        const int r = idx >> 4, u = idx & 15;
        const int phys = ((u ^ (r & 7)) * 16);
        const size_t gk = ((size_t)(j * 64 + r) * NKV + kvh) * HD + u * 8;
        CP_ASYNC16(stage + AT_KH + r * 256 + phys, Kh + gk);
        CP_ASYNC16(stage + AT_KL + r * 256 + phys, Kl + gk);
    }
    for (int idx = tid; idx < 1024; idx += 256) {
        const int r = idx >> 3, u = idx & 7;
        const int phys = ((u ^ (r & 7)) * 16);
        const size_t gv = ((size_t)(kvh * 128 + r)) * SEQ + j * 64 + u * 8;
        CP_ASYNC16(stage + AT_VH + r * 128 + phys, Vth + gv);
        CP_ASYNC16(stage + AT_VL + r * 128 + phys, Vtl + gv);
    }
}

__global__ void __launch_bounds__(256, 1)
attn_hmma_kernel(const __nv_bfloat16* __restrict__ Qh,
                 const __nv_bfloat16* __restrict__ Ql,
                 const __nv_bfloat16* __restrict__ Kh,
                 const __nv_bfloat16* __restrict__ Kl,
                 const __nv_bfloat16* __restrict__ Vth,
                 const __nv_bfloat16* __restrict__ Vtl,
                 float* __restrict__ Y)
{
    extern __shared__ char smraw[];
    const uint32_t sb = smem_u32(smraw);

    const int qt  = blockIdx.x;            // q block of 128 rows (0..15)
    const int h   = blockIdx.y;
    const int kvh = h >> 2;
    const int tid = threadIdx.x;
    const int lid = tid & 31;
    const int wid = tid >> 5;              // 0..7, warp owns rows wid*16..+15
    const int qrow0 = qt * 128;

    // Q tile (128 x 128 bf16 hi+lo)
    for (int idx = tid; idx < 2048; idx += 256) {
        const int r = idx >> 4, u = idx & 15;
        const int phys = ((u ^ (r & 7)) * 16);
        const size_t g = ((size_t)(qrow0 + r) * NH + h) * HD + u * 8;
        CP_ASYNC16(sb + AT_QH + r * 256 + phys, Qh + g);
        CP_ASYNC16(sb + AT_QL + r * 256 + phys, Ql + g);
    }
    attn_load_kv(sb + AT_ST(0), Kh, Kl, Vth, Vtl, 0, kvh, tid);
    CP_COMMIT();

    float o[16][4];
#pragma unroll
    for (int dt = 0; dt < 16; dt++)
#pragma unroll
        for (int q = 0; q < 4; q++) o[dt][q] = 0.f;
    float mA = -1e30f, mB = -1e30f, lA = 0.f, lB = 0.f;

    const int g  = lid >> 2;
    const int cA = (lid & 3) * 2;
    const int jEnd = 2 * qt + 1;           // inclusive

    for (int j = 0; j <= jEnd; j++) {
        CP_WAIT0();
        __syncthreads();
        if (j < jEnd) {
            attn_load_kv(sb + AT_ST((j + 1) & 1), Kh, Kl, Vth, Vtl, j + 1, kvh, tid);
            CP_COMMIT();
        }
        const uint32_t kb = sb + AT_ST(j & 1);

        // ---- S = Q K^T (split) ----
        float s[8][4];
#pragma unroll
        for (int nt = 0; nt < 8; nt++)
#pragma unroll
            for (int q = 0; q < 4; q++) s[nt][q] = 0.f;

#pragma unroll
        for (int kc = 0; kc < 8; kc++) {
            uint32_t qhf[4], qlf[4];
            const int rA = wid * 16 + (lid & 15);
            const int uA = kc * 2 + (lid >> 4);
            ldsm_x4(qhf, sb + AT_QH + rA * 256 + ((uA ^ (rA & 7)) * 16));
            ldsm_x4(qlf, sb + AT_QL + rA * 256 + ((uA ^ (rA & 7)) * 16));
#pragma unroll
            for (int np = 0; np < 4; np++) {
                uint32_t khf[4], klf[4];
                const int rB = np * 16 + ((lid >> 4) & 1) * 8 + (lid & 7);
                const int uB = kc * 2 + ((lid >> 3) & 1);
                ldsm_x4(khf, kb + AT_KH + rB * 256 + ((uB ^ (rB & 7)) * 16));
                ldsm_x4(klf, kb + AT_KL + rB * 256 + ((uB ^ (rB & 7)) * 16));
#pragma unroll
                for (int hf = 0; hf < 2; hf++) {
                    const int nt = np * 2 + hf;
                    mma16816(s[nt], qhf, khf[hf * 2], khf[hf * 2 + 1]);
                    mma16816(s[nt], qhf, klf[hf * 2], klf[hf * 2 + 1]);
                    mma16816(s[nt], qlf, khf[hf * 2], khf[hf * 2 + 1]);
                }
            }
        }

        // ---- causal mask (tiles overlapping the diagonal) ----
        if (j >= 2 * qt) {
            const int rowA = qrow0 + wid * 16 + g;
            const int colBase = j * 64;
#pragma unroll
            for (int nt = 0; nt < 8; nt++) {
                const int col = colBase + nt * 8 + cA;
                if (col     > rowA)     s[nt][0] = -1e30f;
                if (col + 1 > rowA)     s[nt][1] = -1e30f;
                if (col     > rowA + 8) s[nt][2] = -1e30f;
                if (col + 1 > rowA + 8) s[nt][3] = -1e30f;
            }
        }

        // ---- online softmax (fp32 p, split to Ph+Pl) ----
        float mxA = -1e30f, mxB = -1e30f;
#pragma unroll
        for (int nt = 0; nt < 8; nt++) {
            mxA = fmaxf(mxA, fmaxf(s[nt][0], s[nt][1]));
            mxB = fmaxf(mxB, fmaxf(s[nt][2], s[nt][3]));
        }
        mxA = fmaxf(mxA, __shfl_xor_sync(0xffffffffu, mxA, 1));
        mxA = fmaxf(mxA, __shfl_xor_sync(0xffffffffu, mxA, 2));
        mxB = fmaxf(mxB, __shfl_xor_sync(0xffffffffu, mxB, 1));
        mxB = fmaxf(mxB, __shfl_xor_sync(0xffffffffu, mxB, 2));
        const float mnA = fmaxf(mA, mxA), mnB = fmaxf(mB, mxB);
        const float alA = __expf(mA - mnA), alB = __expf(mB - mnB);

        uint32_t ph[8][2], pl[8][2];
        float rsA = 0.f, rsB = 0.f;
#pragma unroll
        for (int nt = 0; nt < 8; nt++) {
            float p0 = __expf(s[nt][0] - mnA);
            float p1 = __expf(s[nt][1] - mnA);
            float p2 = __expf(s[nt][2] - mnB);
            float p3 = __expf(s[nt][3] - mnB);
            rsA += p0 + p1;  rsB += p2 + p3;
            __nv_bfloat16 h0, h1, h2, h3, e0, e1, e2, e3;
            split2(p0, h0, e0); split2(p1, h1, e1);
            split2(p2, h2, e2); split2(p3, h3, e3);
            __nv_bfloat162 a0(h0, h1), a1(h2, h3), b0(e0, e1), b1(e2, e3);
            ph[nt][0] = *reinterpret_cast<uint32_t*>(&a0);
            ph[nt][1] = *reinterpret_cast<uint32_t*>(&a1);
            pl[nt][0] = *reinterpret_cast<uint32_t*>(&b0);
            pl[nt][1] = *reinterpret_cast<uint32_t*>(&b1);
        }
        rsA += __shfl_xor_sync(0xffffffffu, rsA, 1);
        rsA += __shfl_xor_sync(0xffffffffu, rsA, 2);
        rsB += __shfl_xor_sync(0xffffffffu, rsB, 1);
        rsB += __shfl_xor_sync(0xffffffffu, rsB, 2);
        lA = lA * alA + rsA;  mA = mnA;
        lB = lB * alB + rsB;  mB = mnB;

#pragma unroll
        for (int dt = 0; dt < 16; dt++) {
            o[dt][0] *= alA; o[dt][1] *= alA;
            o[dt][2] *= alB; o[dt][3] *= alB;
        }

        // ---- O += Ph.Vh + Pl.Vh + Ph.Vl ----
#pragma unroll
        for (int kc = 0; kc < 4; kc++) {
            uint32_t aH[4] = { ph[2 * kc][0], ph[2 * kc][1],
                               ph[2 * kc + 1][0], ph[2 * kc + 1][1] };
            uint32_t aL[4] = { pl[2 * kc][0], pl[2 * kc][1],
                               pl[2 * kc + 1][0], pl[2 * kc + 1][1] };
#pragma unroll
            for (int dp = 0; dp < 8; dp++) {
                uint32_t vhf[4], vlf[4];
                const int rB = dp * 16 + ((lid >> 4) & 1) * 8 + (lid & 7);
                const int uB = kc * 2 + ((lid >> 3) & 1);
                ldsm_x4(vhf, kb + AT_VH + rB * 128 + ((uB ^ (rB & 7)) * 16));
                ldsm_x4(vlf, kb + AT_VL + rB * 128 + ((uB ^ (rB & 7)) * 16));
#pragma unroll
                for (int hf = 0; hf < 2; hf++) {
                    const int dt = dp * 2 + hf;
                    mma16816(o[dt], aH, vhf[hf * 2], vhf[hf * 2 + 1]);
                    mma16816(o[dt], aL, vhf[hf * 2], vhf[hf * 2 + 1]);
                    mma16816(o[dt], aH, vlf[hf * 2], vlf[hf * 2 + 1]);
                }
            }
        }
    }

    // Epilogue
    const float invA = 1.f / lA, invB = 1.f / lB;
    const int rowA = qrow0 + wid * 16 + g;
#pragma unroll
    for (int dt = 0; dt < 16; dt++) {
        const int d = h * HD + dt * 8 + cA;
        *(float2*)&Y[(size_t)rowA * DIM + d] =
            make_float2(o[dt][0] * invA, o[dt][1] * invA);
        *(float2*)&Y[(size_t)(rowA + 8) * DIM + d] =
            make_float2(o[dt][2] * invB, o[dt][3] * invB);
    }
}

// ---------------------------------------------------------------------------
// Launch
// ---------------------------------------------------------------------------
extern "C" void kernel_launch(void* const* d_in, const int* in_sizes, int n_in,
                              void* d_out, int out_size)
{
    const float* x  = (const float*)d_in[0];
    const float* fc = (const float*)d_in[1];
    const float* wq = (const float*)d_in[3];
    const float* wk = (const float*)d_in[4];
    const float* wv = (const float*)d_in[5];
    const float* wo = (const float*)d_in[6];
    float* out = (float*)d_out;

    float *Q, *Kp, *Vp, *Yp;
    cudaGetSymbolAddress((void**)&Q,  g_q);
    cudaGetSymbolAddress((void**)&Kp, g_k);
    cudaGetSymbolAddress((void**)&Vp, g_v);
    cudaGetSymbolAddress((void**)&Yp, g_y);

    __nv_bfloat16 *xh, *xl, *wqh, *wql, *wkh, *wkl, *wvh, *wvl, *woh, *wol, *yh, *yl;
    __nv_bfloat16 *qh, *ql, *kh, *kl, *vth, *vtl;
    cudaGetSymbolAddress((void**)&xh,  g_xh);  cudaGetSymbolAddress((void**)&xl,  g_xl);
    cudaGetSymbolAddress((void**)&wqh, g_wqh); cudaGetSymbolAddress((void**)&wql, g_wql);
    cudaGetSymbolAddress((void**)&wkh, g_wkh); cudaGetSymbolAddress((void**)&wkl, g_wkl);
    cudaGetSymbolAddress((void**)&wvh, g_wvh); cudaGetSymbolAddress((void**)&wvl, g_wvl);
    cudaGetSymbolAddress((void**)&woh, g_woh); cudaGetSymbolAddress((void**)&wol, g_wol);
    cudaGetSymbolAddress((void**)&yh,  g_yh);  cudaGetSymbolAddress((void**)&yl,  g_yl);
    cudaGetSymbolAddress((void**)&qh,  g_qh);  cudaGetSymbolAddress((void**)&ql,  g_ql);
    cudaGetSymbolAddress((void**)&kh,  g_kh);  cudaGetSymbolAddress((void**)&kl,  g_kl);
    cudaGetSymbolAddress((void**)&vth, g_vth); cudaGetSymbolAddress((void**)&vtl, g_vtl);

    cudaFuncSetAttribute(gemm_qkv_kernel,
                         cudaFuncAttributeMaxDynamicSharedMemorySize, GEMM_SMEM);
    cudaFuncSetAttribute(gemm_hmma_kernel,
                         cudaFuncAttributeMaxDynamicSharedMemorySize, GEMM_SMEM);
    cudaFuncSetAttribute(attn_hmma_kernel,
                         cudaFuncAttributeMaxDynamicSharedMemorySize, AT_SMEM);

    const int T = 256;
    split_kernel<<<(SEQ * DIM / 8 + T - 1) / T, T>>>(x,  xh,  xl,  SEQ * DIM / 8);
    split_kernel<<<(DIM * DIM / 8 + T - 1) / T, T>>>(wq, wqh, wql, DIM * DIM / 8);
    split_kernel<<<(KVDIM * DIM / 8 + T - 1) / T, T>>>(wk, wkh, wkl, KVDIM * DIM / 8);
    split_kernel<<<(KVDIM * DIM / 8 + T - 1) / T, T>>>(wv, wvh, wvl, KVDIM * DIM / 8);
    split_kernel<<<(DIM * DIM / 8 + T - 1) / T, T>>>(wo, woh, wol, DIM * DIM / 8);

    // Fused QKV projection (24 col blocks x 16 row blocks)
    gemm_qkv_kernel<<<dim3(24, SEQ / 128), 256, GEMM_SMEM>>>(
        xh, xl, wqh, wql, wkh, wkl, wvh, wvl, Q, Kp, Vp);

    // RoPE + split; V transpose + split
    const float scale = 0.08838834764831845f;
    rope_split_kernel<<<(SEQ * NH  * 64 + T - 1) / T, T>>>(
        Q,  fc, qh, ql, NH,  scale, SEQ * NH  * 64);
    rope_split_kernel<<<(SEQ * NKV * 64 + T - 1) / T, T>>>(
        Kp, fc, kh, kl, NKV, 1.0f,  SEQ * NKV * 64);
    split_vt_kernel<<<(KVDIM * SEQ + T - 1) / T, T>>>(Vp, vth, vtl);

    // Attention (Br=128)
    attn_hmma_kernel<<<dim3(SEQ / 128, NH), 256, AT_SMEM>>>(
        qh, ql, kh, kl, vth, vtl, Yp);

    // Output projection
    split_kernel<<<(SEQ * DIM / 8 + T - 1) / T, T>>>(Yp, yh, yl, SEQ * DIM / 8);
    gemm_hmma_kernel<<<dim3(DIM / 256, SEQ / 128), 256, GEMM_SMEM>>>(
        yh, yl, woh, wol, out, DIM);
}